// round 1
// baseline (speedup 1.0000x reference)
#include <cuda_runtime.h>
#include <math.h>

#define DM 768
#define BB 32
#define SS 512
#define MR (BB*SS)          // 16384 rows
#define NEL (MR*DM)         // 12582912 elements per [B,S,D] tensor

// ---------------- scratch (static device globals; no allocation) ----------------
static __device__ float g_embv[NEL];
static __device__ float g_emba[NEL];
static __device__ float g_q[NEL];
static __device__ float g_k[NEL];
static __device__ float g_v[NEL];
static __device__ float g_vatt[NEL];
static __device__ float g_aatt[NEL];
static __device__ float g_v2[NEL];
static __device__ float g_a2[NEL];
static __device__ float g_F1[NEL];
static __device__ float g_F2[NEL];
static __device__ float g_F3[NEL];
static __device__ float g_t1[NEL];
static __device__ float g_t2[NEL];
static __device__ float g_scores[67108864];   // B*8*S*S fp32 = 256 MB (covers 1-head case too)

// ---------------- elementwise kernels ----------------

__global__ void __launch_bounds__(256) embed_kernel(
    const float* __restrict__ tab, const int* __restrict__ ids, float* __restrict__ out)
{
    int i = blockIdx.x * 256 + threadIdx.x;
    if (i >= NEL) return;
    int row = i / DM;
    int d = i - row * DM;
    out[i] = tab[(size_t)ids[row] * DM + d];
}

// interleaved RoPE over full hidden dim; position = row % S
__global__ void __launch_bounds__(256) rope_kernel(float* __restrict__ x)
{
    int i = blockIdx.x * 256 + threadIdx.x;
    if (i >= MR * (DM / 2)) return;
    int row = i / (DM / 2);
    int j = i - row * (DM / 2);
    int s = row & (SS - 1);
    // theta = 10000^(-2j/768) = 2^(j * (-2*log2(10000)/768))
    const float coef = -0.034603417655075f; // -2*log2(10000)/768
    float theta = exp2f(coef * (float)j);
    float ang = (float)s * theta;
    float sn, c;
    sincosf(ang, &sn, &c);
    float* p = x + (size_t)row * DM + 2 * j;
    float x0 = p[0], x1 = p[1];
    p[0] = x0 * c - x1 * sn;
    p[1] = x1 * c + x0 * sn;
}

__global__ void __launch_bounds__(256) add4_kernel(
    const float* __restrict__ a, const float* __restrict__ b,
    const float* __restrict__ c, const float* __restrict__ d, float* __restrict__ o)
{
    int i = blockIdx.x * 256 + threadIdx.x;
    if (i < NEL) o[i] = a[i] + b[i] + c[i] + d[i];
}

// ---------------- row softmax over 512 (attention scores), in-place ----------------
__global__ void __launch_bounds__(256) softmax512_kernel(float* __restrict__ x)
{
    __shared__ float shm[8];
    __shared__ float shs[8];
    size_t row = blockIdx.x;
    float* p = x + row * 512;
    int t = threadIdx.x;
    int lane = t & 31, wid = t >> 5;

    float a = p[t], b = p[t + 256];
    float m = fmaxf(a, b);
    #pragma unroll
    for (int o = 16; o; o >>= 1) m = fmaxf(m, __shfl_xor_sync(0xffffffffu, m, o));
    if (lane == 0) shm[wid] = m;
    __syncthreads();
    float m2 = shm[0];
    #pragma unroll
    for (int i = 1; i < 8; i++) m2 = fmaxf(m2, shm[i]);

    float e0 = __expf(a - m2), e1 = __expf(b - m2);
    float s = e0 + e1;
    #pragma unroll
    for (int o = 16; o; o >>= 1) s += __shfl_xor_sync(0xffffffffu, s, o);
    if (lane == 0) shs[wid] = s;
    __syncthreads();
    float s2 = 0.f;
    #pragma unroll
    for (int i = 0; i < 8; i++) s2 += shs[i];
    float inv = 1.f / s2;
    p[t] = e0 * inv;
    p[t + 256] = e1 * inv;
}

// ---------------- gate: out = x + x*softmax_row(x), rows of 768 ----------------
__global__ void __launch_bounds__(256) gate_kernel(
    const float* __restrict__ in, float* __restrict__ out)
{
    __shared__ float shm[8];
    __shared__ float shs[8];
    size_t row = blockIdx.x;
    const float* p = in + row * 768;
    float* q = out + row * 768;
    int t = threadIdx.x;
    int lane = t & 31, wid = t >> 5;

    float a = p[t], b = p[t + 256], c = p[t + 512];
    float m = fmaxf(fmaxf(a, b), c);
    #pragma unroll
    for (int o = 16; o; o >>= 1) m = fmaxf(m, __shfl_xor_sync(0xffffffffu, m, o));
    if (lane == 0) shm[wid] = m;
    __syncthreads();
    float m2 = shm[0];
    #pragma unroll
    for (int i = 1; i < 8; i++) m2 = fmaxf(m2, shm[i]);

    float e0 = __expf(a - m2), e1 = __expf(b - m2), e2 = __expf(c - m2);
    float s = e0 + e1 + e2;
    #pragma unroll
    for (int o = 16; o; o >>= 1) s += __shfl_xor_sync(0xffffffffu, s, o);
    if (lane == 0) shs[wid] = s;
    __syncthreads();
    float s2 = 0.f;
    #pragma unroll
    for (int i = 0; i < 8; i++) s2 += shs[i];
    float inv = 1.f / s2;
    q[t]       = a + a * e0 * inv;
    q[t + 256] = b + b * e1 * inv;
    q[t + 512] = c + c * e2 * inv;
}

// ---------------- main SGEMM: C[M,N] = A[M,K] @ W[K,N] + bias, optional silu ----------------
// 128x128 tile, BK=8, 256 threads, 8x8 microtile. M=16384, N=768, K in {768}.
template <int EPI>  // 0: bias, 1: bias+silu
__global__ void __launch_bounds__(256) sgemm_kernel(
    const float* __restrict__ A, const float* __restrict__ W,
    const float* __restrict__ bias, float* __restrict__ C, int K, int N)
{
    __shared__ float As[8][128];
    __shared__ float Bs[8][128];
    const int tid = threadIdx.x;
    const int rowStart = blockIdx.y * 128, colStart = blockIdx.x * 128;
    const int tx = tid & 15, ty = tid >> 4;
    const int aRow = tid >> 1, aCol = (tid & 1) * 4;
    const int bRow = tid >> 5, bCol = (tid & 31) * 4;
    const float* Aptr = A + (size_t)(rowStart + aRow) * K + aCol;
    const float* Wptr = W + (size_t)bRow * N + colStart + bCol;

    float acc[8][8];
    #pragma unroll
    for (int i = 0; i < 8; i++)
        #pragma unroll
        for (int j = 0; j < 8; j++) acc[i][j] = 0.f;

    for (int k0 = 0; k0 < K; k0 += 8) {
        float4 av = *(const float4*)Aptr;
        As[aCol + 0][aRow] = av.x;
        As[aCol + 1][aRow] = av.y;
        As[aCol + 2][aRow] = av.z;
        As[aCol + 3][aRow] = av.w;
        *(float4*)&Bs[bRow][bCol] = *(const float4*)Wptr;
        __syncthreads();
        #pragma unroll
        for (int kk = 0; kk < 8; kk++) {
            float ra[8], rb[8];
            *(float4*)&ra[0] = *(const float4*)&As[kk][ty * 8];
            *(float4*)&ra[4] = *(const float4*)&As[kk][ty * 8 + 4];
            *(float4*)&rb[0] = *(const float4*)&Bs[kk][tx * 8];
            *(float4*)&rb[4] = *(const float4*)&Bs[kk][tx * 8 + 4];
            #pragma unroll
            for (int i = 0; i < 8; i++)
                #pragma unroll
                for (int j = 0; j < 8; j++)
                    acc[i][j] = fmaf(ra[i], rb[j], acc[i][j]);
        }
        __syncthreads();
        Aptr += 8;
        Wptr += (size_t)8 * N;
    }
    #pragma unroll
    for (int i = 0; i < 8; i++) {
        int r = rowStart + ty * 8 + i;
        #pragma unroll
        for (int j = 0; j < 8; j++) {
            int c = colStart + tx * 8 + j;
            float v = acc[i][j] + bias[c];
            if (EPI == 1) v = v * (1.f / (1.f + __expf(-v)));   // silu
            C[(size_t)r * N + c] = v;
        }
    }
}

// concat GEMM: C = [A1 | A2] @ W(1536x768) + bias
__global__ void __launch_bounds__(256) sgemm_cat_kernel(
    const float* __restrict__ A1, const float* __restrict__ A2,
    const float* __restrict__ W, const float* __restrict__ bias, float* __restrict__ C)
{
    __shared__ float As[8][128];
    __shared__ float Bs[8][128];
    const int tid = threadIdx.x;
    const int rowStart = blockIdx.y * 128, colStart = blockIdx.x * 128;
    const int tx = tid & 15, ty = tid >> 4;
    const int aRow = tid >> 1, aCol = (tid & 1) * 4;
    const int bRow = tid >> 5, bCol = (tid & 31) * 4;
    const float* Wptr = W + (size_t)bRow * 768 + colStart + bCol;

    float acc[8][8];
    #pragma unroll
    for (int i = 0; i < 8; i++)
        #pragma unroll
        for (int j = 0; j < 8; j++) acc[i][j] = 0.f;

    for (int k0 = 0; k0 < 1536; k0 += 8) {
        int kc = k0 + aCol;
        const float* src = (kc < 768)
            ? (A1 + (size_t)(rowStart + aRow) * 768 + kc)
            : (A2 + (size_t)(rowStart + aRow) * 768 + (kc - 768));
        float4 av = *(const float4*)src;
        As[aCol + 0][aRow] = av.x;
        As[aCol + 1][aRow] = av.y;
        As[aCol + 2][aRow] = av.z;
        As[aCol + 3][aRow] = av.w;
        *(float4*)&Bs[bRow][bCol] = *(const float4*)Wptr;
        __syncthreads();
        #pragma unroll
        for (int kk = 0; kk < 8; kk++) {
            float ra[8], rb[8];
            *(float4*)&ra[0] = *(const float4*)&As[kk][ty * 8];
            *(float4*)&ra[4] = *(const float4*)&As[kk][ty * 8 + 4];
            *(float4*)&rb[0] = *(const float4*)&Bs[kk][tx * 8];
            *(float4*)&rb[4] = *(const float4*)&Bs[kk][tx * 8 + 4];
            #pragma unroll
            for (int i = 0; i < 8; i++)
                #pragma unroll
                for (int j = 0; j < 8; j++)
                    acc[i][j] = fmaf(ra[i], rb[j], acc[i][j]);
        }
        __syncthreads();
        Wptr += (size_t)8 * 768;
    }
    #pragma unroll
    for (int i = 0; i < 8; i++) {
        int r = rowStart + ty * 8 + i;
        #pragma unroll
        for (int j = 0; j < 8; j++) {
            int c = colStart + tx * 8 + j;
            C[(size_t)r * 768 + c] = acc[i][j] + bias[c];
        }
    }
}

// ---------------- scores = 8 * Q @ K^T per (b,h). 128x128 tiles, BK=8 ----------------
__global__ void __launch_bounds__(256) score_kernel(
    const float* __restrict__ Q, const float* __restrict__ Kmat,
    float* __restrict__ Sc, int H, int hd)
{
    const int bh = blockIdx.z;
    const int b = bh / H, h = bh - b * H;
    const float* A = Q + (size_t)b * SS * DM + h * hd;
    const float* Bm = Kmat + (size_t)b * SS * DM + h * hd;
    float* C = Sc + (size_t)bh * SS * SS;

    __shared__ float As[8][128];
    __shared__ float Bs[8][128];
    const int tid = threadIdx.x;
    const int rowStart = blockIdx.y * 128, colStart = blockIdx.x * 128;
    const int tx = tid & 15, ty = tid >> 4;
    const int aRow = tid >> 1, aCol = (tid & 1) * 4;
    const float* Aptr = A + (size_t)(rowStart + aRow) * DM + aCol;
    const float* Bptr = Bm + (size_t)(colStart + aRow) * DM + aCol;

    float acc[8][8];
    #pragma unroll
    for (int i = 0; i < 8; i++)
        #pragma unroll
        for (int j = 0; j < 8; j++) acc[i][j] = 0.f;

    for (int k0 = 0; k0 < hd; k0 += 8) {
        float4 av = *(const float4*)Aptr;
        As[aCol + 0][aRow] = av.x;
        As[aCol + 1][aRow] = av.y;
        As[aCol + 2][aRow] = av.z;
        As[aCol + 3][aRow] = av.w;
        float4 bv = *(const float4*)Bptr;
        Bs[aCol + 0][aRow] = bv.x;
        Bs[aCol + 1][aRow] = bv.y;
        Bs[aCol + 2][aRow] = bv.z;
        Bs[aCol + 3][aRow] = bv.w;
        __syncthreads();
        #pragma unroll
        for (int kk = 0; kk < 8; kk++) {
            float ra[8], rb[8];
            *(float4*)&ra[0] = *(const float4*)&As[kk][ty * 8];
            *(float4*)&ra[4] = *(const float4*)&As[kk][ty * 8 + 4];
            *(float4*)&rb[0] = *(const float4*)&Bs[kk][tx * 8];
            *(float4*)&rb[4] = *(const float4*)&Bs[kk][tx * 8 + 4];
            #pragma unroll
            for (int i = 0; i < 8; i++)
                #pragma unroll
                for (int j = 0; j < 8; j++)
                    acc[i][j] = fmaf(ra[i], rb[j], acc[i][j]);
        }
        __syncthreads();
        Aptr += 8;
        Bptr += 8;
    }
    #pragma unroll
    for (int i = 0; i < 8; i++) {
        int r = rowStart + ty * 8 + i;
        #pragma unroll
        for (int j = 0; j < 8; j++) {
            int c = colStart + tx * 8 + j;
            C[(size_t)r * SS + c] = 8.f * acc[i][j];
        }
    }
}

// ---------------- out_head = P @ V_head per (b,h). 128x96 tiles, BK=8 ----------------
__global__ void __launch_bounds__(256) pv_kernel(
    const float* __restrict__ P, const float* __restrict__ V,
    float* __restrict__ Out, int H, int hd)
{
    const int bh = blockIdx.z;
    const int b = bh / H, h = bh - b * H;
    const float* Pp = P + (size_t)bh * SS * SS;
    const float* Vp = V + (size_t)b * SS * DM + h * hd;

    __shared__ float Ps[8][128];
    __shared__ float Vs[8][96];
    const int tid = threadIdx.x;
    const int rowStart = blockIdx.y * 128, colStart = blockIdx.x * 96;
    const int tx = tid & 15, ty = tid >> 4;
    const int aRow = tid >> 1, aCol = (tid & 1) * 4;
    const float* Aptr = Pp + (size_t)(rowStart + aRow) * SS + aCol;
    const int vRow = tid / 24, vCol = (tid % 24) * 4;   // 192 active threads

    float acc[8][6];
    #pragma unroll
    for (int i = 0; i < 8; i++)
        #pragma unroll
        for (int j = 0; j < 6; j++) acc[i][j] = 0.f;

    for (int k0 = 0; k0 < SS; k0 += 8) {
        float4 av = *(const float4*)Aptr;
        Ps[aCol + 0][aRow] = av.x;
        Ps[aCol + 1][aRow] = av.y;
        Ps[aCol + 2][aRow] = av.z;
        Ps[aCol + 3][aRow] = av.w;
        if (tid < 192) {
            float4 vv = *(const float4*)(Vp + (size_t)(k0 + vRow) * DM + colStart + vCol);
            *(float4*)&Vs[vRow][vCol] = vv;
        }
        __syncthreads();
        #pragma unroll
        for (int kk = 0; kk < 8; kk++) {
            float ra[8], rb[6];
            *(float4*)&ra[0] = *(const float4*)&Ps[kk][ty * 8];
            *(float4*)&ra[4] = *(const float4*)&Ps[kk][ty * 8 + 4];
            #pragma unroll
            for (int j = 0; j < 6; j++) rb[j] = Vs[kk][tx * 6 + j];
            #pragma unroll
            for (int i = 0; i < 8; i++)
                #pragma unroll
                for (int j = 0; j < 6; j++)
                    acc[i][j] = fmaf(ra[i], rb[j], acc[i][j]);
        }
        __syncthreads();
        Aptr += 8;
    }
    #pragma unroll
    for (int i = 0; i < 8; i++) {
        int r = rowStart + ty * 8 + i;
        #pragma unroll
        for (int j = 0; j < 6; j++) {
            int c = h * hd + colStart + tx * 6 + j;
            Out[((size_t)b * SS + r) * DM + c] = acc[i][j];
        }
    }
}

// ---------------- host ----------------

extern "C" void kernel_launch(void* const* d_in, const int* in_sizes, int n_in,
                              void* d_out, int out_size)
{
    (void)n_in; (void)out_size;
    const float *text, *vtab, *atab;
    const float *aw[18];  // hv(wq,bq,wk,bk,wv,bv), ha(...), ht(...)
    const float *fcw, *fcb, *f1w, *f1b, *f2w, *f2b, *catw, *catb;
    const int *vid, *aid;

    if (in_sizes[1] == MR) {
        // setup_inputs() dict order
        text = (const float*)d_in[0];
        vid  = (const int*)d_in[1];
        aid  = (const int*)d_in[2];
        vtab = (const float*)d_in[3];
        atab = (const float*)d_in[4];
        for (int i = 0; i < 18; i++) aw[i] = (const float*)d_in[5 + i];
        fcw = (const float*)d_in[23]; fcb = (const float*)d_in[24];
        f1w = (const float*)d_in[25]; f1b = (const float*)d_in[26];
        f2w = (const float*)d_in[27]; f2b = (const float*)d_in[28];
        catw = (const float*)d_in[29]; catb = (const float*)d_in[30];
    } else {
        // reference() signature order
        text = (const float*)d_in[0];
        vtab = (const float*)d_in[1];
        atab = (const float*)d_in[2];
        for (int i = 0; i < 18; i++) aw[i] = (const float*)d_in[3 + i];
        fcw = (const float*)d_in[21]; fcb = (const float*)d_in[22];
        f1w = (const float*)d_in[23]; f1b = (const float*)d_in[24];
        f2w = (const float*)d_in[25]; f2b = (const float*)d_in[26];
        catw = (const float*)d_in[27]; catb = (const float*)d_in[28];
        vid  = (const int*)d_in[29];
        aid  = (const int*)d_in[30];
    }

    float *embv, *emba, *q, *k, *v, *vatt, *aatt, *v2, *a2, *F1, *F2, *F3, *t1, *t2, *sc;
    cudaGetSymbolAddress((void**)&embv, g_embv);
    cudaGetSymbolAddress((void**)&emba, g_emba);
    cudaGetSymbolAddress((void**)&q, g_q);
    cudaGetSymbolAddress((void**)&k, g_k);
    cudaGetSymbolAddress((void**)&v, g_v);
    cudaGetSymbolAddress((void**)&vatt, g_vatt);
    cudaGetSymbolAddress((void**)&aatt, g_aatt);
    cudaGetSymbolAddress((void**)&v2, g_v2);
    cudaGetSymbolAddress((void**)&a2, g_a2);
    cudaGetSymbolAddress((void**)&F1, g_F1);
    cudaGetSymbolAddress((void**)&F2, g_F2);
    cudaGetSymbolAddress((void**)&F3, g_F3);
    cudaGetSymbolAddress((void**)&t1, g_t1);
    cudaGetSymbolAddress((void**)&t2, g_t2);
    cudaGetSymbolAddress((void**)&sc, g_scores);

    const dim3 gGemm(6, 128);
    const int EW = (NEL + 255) / 256;
    const int RW = (MR * (DM / 2) + 255) / 256;

    auto GEMM = [&](const float* A, const float* Wm, const float* bi, float* Cc) {
        sgemm_kernel<0><<<gGemm, 256>>>(A, Wm, bi, Cc, 768, 768);
    };
    auto ROPE = [&](float* x) { rope_kernel<<<RW, 256>>>(x); };
    auto ATT1 = [&](const float* qin, const float* kvin, const float* const* w6, float* outb) {
        GEMM(qin, w6[0], w6[1], q);  ROPE(q);
        GEMM(kvin, w6[2], w6[3], k); ROPE(k);
        GEMM(kvin, w6[4], w6[5], v);
        score_kernel<<<dim3(4, 4, 32), 256>>>(q, k, sc, 1, 768);
        softmax512_kernel<<<BB * SS, 256>>>(sc);
        pv_kernel<<<dim3(8, 4, 32), 256>>>(sc, v, outb, 1, 768);
    };
    auto FFN = [&](float* x) {  // x = ffn(gate(x))
        gate_kernel<<<MR, 256>>>(x, t1);
        sgemm_kernel<1><<<gGemm, 256>>>(t1, f1w, f1b, t2, 768, 768);
        sgemm_kernel<0><<<gGemm, 256>>>(t2, f2w, f2b, x, 768, 768);
    };

    // embeddings
    embed_kernel<<<EW, 256>>>(vtab, vid, embv);
    embed_kernel<<<EW, 256>>>(atab, aid, emba);

    // stage 1: visual_ = hv(text, emb_v); acoustic_ = ha(text, emb_a)
    ATT1(text, embv, &aw[0], vatt);
    ATT1(text, emba, &aw[6], aatt);

    // F1 = ffn(gate(cat(visual_, acoustic_) @ cat_w + b))
    sgemm_cat_kernel<<<gGemm, 256>>>(vatt, aatt, catw, catb, F1);
    FFN(F1);

    // stage 2: v = hv(visual_, acoustic_); a = ha(acoustic_, visual_)
    ATT1(vatt, aatt, &aw[0], v2);
    ATT1(aatt, vatt, &aw[6], a2);
    sgemm_cat_kernel<<<gGemm, 256>>>(v2, a2, catw, catb, F2);
    FFN(F2);

    // stage 3: F3 = mh8(F1, text) @ fcw + fcb, then ffn(gate(...))
    GEMM(F1, aw[12], aw[13], q);  ROPE(q);
    GEMM(text, aw[14], aw[15], k); ROPE(k);
    GEMM(text, aw[16], aw[17], v);
    score_kernel<<<dim3(4, 4, 256), 256>>>(q, k, sc, 8, 96);
    softmax512_kernel<<<BB * 8 * SS, 256>>>(sc);
    pv_kernel<<<dim3(1, 4, 256), 256>>>(sc, v, t1, 8, 96);
    GEMM(t1, fcw, fcb, F3);
    FFN(F3);

    // es = text + F1 + F2 + F3; out = gate(es)
    add4_kernel<<<EW, 256>>>(text, F1, F2, F3, t1);
    gate_kernel<<<MR, 256>>>(t1, (float*)d_out);
}

// round 2
// speedup vs baseline: 1.9458x; 1.9458x over previous
#include <cuda_runtime.h>
#include <math.h>

#define DM 768
#define BB 32
#define SS 512
#define MR (BB*SS)          // 16384 rows
#define NEL (MR*DM)         // 12582912 elements per [B,S,D] tensor

typedef unsigned long long u64;

__device__ __forceinline__ u64 pk2(float lo, float hi) {
    u64 r; asm("mov.b64 %0,{%1,%2};" : "=l"(r) : "f"(lo), "f"(hi)); return r;
}
__device__ __forceinline__ void upk2(u64 v, float& lo, float& hi) {
    asm("mov.b64 {%0,%1},%2;" : "=f"(lo), "=f"(hi) : "l"(v));
}
__device__ __forceinline__ u64 ffma2(u64 a, u64 b, u64 c) {
    u64 d; asm("fma.rn.f32x2 %0,%1,%2,%3;" : "=l"(d) : "l"(a), "l"(b), "l"(c)); return d;
}

// ---------------- scratch (static device globals; no allocation) ----------------
static __device__ float g_embv[NEL];
static __device__ float g_emba[NEL];
static __device__ float g_q[NEL];
static __device__ float g_k[NEL];
static __device__ float g_v[NEL];
static __device__ float g_vatt[NEL];
static __device__ float g_aatt[NEL];
static __device__ float g_v2[NEL];
static __device__ float g_a2[NEL];
static __device__ float g_F1[NEL];
static __device__ float g_F2[NEL];
static __device__ float g_F3[NEL];
static __device__ float g_t1[NEL];
static __device__ float g_t2[NEL];
static __device__ float g_scores[67108864];   // B*8*S*S fp32 = 256 MB

// ---------------- elementwise kernels ----------------

__global__ void __launch_bounds__(256) embed_kernel(
    const float* __restrict__ tab, const int* __restrict__ ids, float* __restrict__ out)
{
    int i = blockIdx.x * 256 + threadIdx.x;
    if (i >= NEL) return;
    int row = i / DM;
    int d = i - row * DM;
    out[i] = tab[(size_t)ids[row] * DM + d];
}

__global__ void __launch_bounds__(256) rope_kernel(float* __restrict__ x)
{
    int i = blockIdx.x * 256 + threadIdx.x;
    if (i >= MR * (DM / 2)) return;
    int row = i / (DM / 2);
    int j = i - row * (DM / 2);
    int s = row & (SS - 1);
    const float coef = -0.034603417655075f; // -2*log2(10000)/768
    float theta = exp2f(coef * (float)j);
    float ang = (float)s * theta;
    float sn, c;
    sincosf(ang, &sn, &c);
    float* p = x + (size_t)row * DM + 2 * j;
    float x0 = p[0], x1 = p[1];
    p[0] = x0 * c - x1 * sn;
    p[1] = x1 * c + x0 * sn;
}

__global__ void __launch_bounds__(256) add4_kernel(
    const float* __restrict__ a, const float* __restrict__ b,
    const float* __restrict__ c, const float* __restrict__ d, float* __restrict__ o)
{
    int i = blockIdx.x * 256 + threadIdx.x;
    if (i < NEL) o[i] = a[i] + b[i] + c[i] + d[i];
}

__global__ void __launch_bounds__(256) softmax512_kernel(float* __restrict__ x)
{
    __shared__ float shm[8];
    __shared__ float shs[8];
    size_t row = blockIdx.x;
    float* p = x + row * 512;
    int t = threadIdx.x;
    int lane = t & 31, wid = t >> 5;

    float a = p[t], b = p[t + 256];
    float m = fmaxf(a, b);
    #pragma unroll
    for (int o = 16; o; o >>= 1) m = fmaxf(m, __shfl_xor_sync(0xffffffffu, m, o));
    if (lane == 0) shm[wid] = m;
    __syncthreads();
    float m2 = shm[0];
    #pragma unroll
    for (int i = 1; i < 8; i++) m2 = fmaxf(m2, shm[i]);

    float e0 = __expf(a - m2), e1 = __expf(b - m2);
    float s = e0 + e1;
    #pragma unroll
    for (int o = 16; o; o >>= 1) s += __shfl_xor_sync(0xffffffffu, s, o);
    if (lane == 0) shs[wid] = s;
    __syncthreads();
    float s2 = 0.f;
    #pragma unroll
    for (int i = 0; i < 8; i++) s2 += shs[i];
    float inv = 1.f / s2;
    p[t] = e0 * inv;
    p[t + 256] = e1 * inv;
}

__global__ void __launch_bounds__(256) gate_kernel(
    const float* __restrict__ in, float* __restrict__ out)
{
    __shared__ float shm[8];
    __shared__ float shs[8];
    size_t row = blockIdx.x;
    const float* p = in + row * 768;
    float* q = out + row * 768;
    int t = threadIdx.x;
    int lane = t & 31, wid = t >> 5;

    float a = p[t], b = p[t + 256], c = p[t + 512];
    float m = fmaxf(fmaxf(a, b), c);
    #pragma unroll
    for (int o = 16; o; o >>= 1) m = fmaxf(m, __shfl_xor_sync(0xffffffffu, m, o));
    if (lane == 0) shm[wid] = m;
    __syncthreads();
    float m2 = shm[0];
    #pragma unroll
    for (int i = 1; i < 8; i++) m2 = fmaxf(m2, shm[i]);

    float e0 = __expf(a - m2), e1 = __expf(b - m2), e2 = __expf(c - m2);
    float s = e0 + e1 + e2;
    #pragma unroll
    for (int o = 16; o; o >>= 1) s += __shfl_xor_sync(0xffffffffu, s, o);
    if (lane == 0) shs[wid] = s;
    __syncthreads();
    float s2 = 0.f;
    #pragma unroll
    for (int i = 0; i < 8; i++) s2 += shs[i];
    float inv = 1.f / s2;
    q[t]       = a + a * e0 * inv;
    q[t + 256] = b + b * e1 * inv;
    q[t + 512] = c + c * e2 * inv;
}

// ---------------- f32x2 SGEMM: C[M,N] = A[M,K] @ W[K,N] + bias, optional silu ----------------
// 128x256 tile, BK=8, 256 threads, 8x16 microtile (8 f32x2 pairs per thread row).
// Thread (ty,tx): rows ty*8..+7, col pairs at col = 2*tx + 32*j (j=0..7) -> LDS.64 + float2
// stores are conflict-free / coalesced.
template <int EPI>  // 0: bias, 1: bias+silu
__global__ void __launch_bounds__(256) sgemm2_kernel(
    const float* __restrict__ A, const float* __restrict__ W,
    const float* __restrict__ bias, float* __restrict__ C, int K, int N)
{
    __shared__ float As[8][128];
    __shared__ float Bs[8][256];
    const int tid = threadIdx.x;
    const int rowStart = blockIdx.y * 128, colStart = blockIdx.x * 256;
    const int tx = tid & 15, ty = tid >> 4;
    const int aRow = tid >> 1, aCol = (tid & 1) * 4;
    const int bRow = tid >> 5, bCol = (tid & 31) * 8;
    const float* Aptr = A + (size_t)(rowStart + aRow) * K + aCol;
    const float* Wptr = W + (size_t)bRow * N + colStart + bCol;

    u64 acc[8][8];
    #pragma unroll
    for (int i = 0; i < 8; i++)
        #pragma unroll
        for (int j = 0; j < 8; j++) acc[i][j] = 0ull;

    float4 aReg = *(const float4*)Aptr;
    float4 bReg0 = *(const float4*)Wptr;
    float4 bReg1 = *(const float4*)(Wptr + 4);

    for (int k0 = 0; k0 < K; k0 += 8) {
        As[aCol + 0][aRow] = aReg.x;
        As[aCol + 1][aRow] = aReg.y;
        As[aCol + 2][aRow] = aReg.z;
        As[aCol + 3][aRow] = aReg.w;
        *(float4*)&Bs[bRow][bCol] = bReg0;
        *(float4*)&Bs[bRow][bCol + 4] = bReg1;
        __syncthreads();
        if (k0 + 8 < K) {
            Aptr += 8;
            Wptr += (size_t)8 * N;
            aReg = *(const float4*)Aptr;
            bReg0 = *(const float4*)Wptr;
            bReg1 = *(const float4*)(Wptr + 4);
        }
        #pragma unroll
        for (int kk = 0; kk < 8; kk++) {
            float4 t0 = *(const float4*)&As[kk][ty * 8];
            float4 t1 = *(const float4*)&As[kk][ty * 8 + 4];
            u64 ra[8] = { pk2(t0.x, t0.x), pk2(t0.y, t0.y), pk2(t0.z, t0.z), pk2(t0.w, t0.w),
                          pk2(t1.x, t1.x), pk2(t1.y, t1.y), pk2(t1.z, t1.z), pk2(t1.w, t1.w) };
            u64 rb[8];
            #pragma unroll
            for (int j = 0; j < 8; j++) {
                float2 bv = *(const float2*)&Bs[kk][2 * tx + 32 * j];
                rb[j] = pk2(bv.x, bv.y);
            }
            #pragma unroll
            for (int i = 0; i < 8; i++)
                #pragma unroll
                for (int j = 0; j < 8; j++)
                    acc[i][j] = ffma2(ra[i], rb[j], acc[i][j]);
        }
        __syncthreads();
    }
    #pragma unroll
    for (int i = 0; i < 8; i++) {
        int r = rowStart + ty * 8 + i;
        float* Crow = C + (size_t)r * N + colStart;
        #pragma unroll
        for (int j = 0; j < 8; j++) {
            int c = 2 * tx + 32 * j;
            float lo, hi;
            upk2(acc[i][j], lo, hi);
            lo += bias[colStart + c];
            hi += bias[colStart + c + 1];
            if (EPI == 1) {
                lo = lo * (1.f / (1.f + __expf(-lo)));
                hi = hi * (1.f / (1.f + __expf(-hi)));
            }
            *(float2*)(Crow + c) = make_float2(lo, hi);
        }
    }
}

// concat GEMM: C = [A1 | A2] @ W(1536x768) + bias, f32x2 version
__global__ void __launch_bounds__(256) sgemm2_cat_kernel(
    const float* __restrict__ A1, const float* __restrict__ A2,
    const float* __restrict__ W, const float* __restrict__ bias, float* __restrict__ C)
{
    __shared__ float As[8][128];
    __shared__ float Bs[8][256];
    const int tid = threadIdx.x;
    const int rowStart = blockIdx.y * 128, colStart = blockIdx.x * 256;
    const int tx = tid & 15, ty = tid >> 4;
    const int aRow = tid >> 1, aCol = (tid & 1) * 4;
    const int bRow = tid >> 5, bCol = (tid & 31) * 8;
    const size_t rowOff = (size_t)(rowStart + aRow) * 768;
    const float* Wptr = W + (size_t)bRow * 768 + colStart + bCol;

    u64 acc[8][8];
    #pragma unroll
    for (int i = 0; i < 8; i++)
        #pragma unroll
        for (int j = 0; j < 8; j++) acc[i][j] = 0ull;

    auto loadA = [&](int k0) -> float4 {
        int kc = k0 + aCol;
        const float* src = (kc < 768) ? (A1 + rowOff + kc) : (A2 + rowOff + kc - 768);
        return *(const float4*)src;
    };

    float4 aReg = loadA(0);
    float4 bReg0 = *(const float4*)Wptr;
    float4 bReg1 = *(const float4*)(Wptr + 4);

    for (int k0 = 0; k0 < 1536; k0 += 8) {
        As[aCol + 0][aRow] = aReg.x;
        As[aCol + 1][aRow] = aReg.y;
        As[aCol + 2][aRow] = aReg.z;
        As[aCol + 3][aRow] = aReg.w;
        *(float4*)&Bs[bRow][bCol] = bReg0;
        *(float4*)&Bs[bRow][bCol + 4] = bReg1;
        __syncthreads();
        if (k0 + 8 < 1536) {
            aReg = loadA(k0 + 8);
            Wptr += (size_t)8 * 768;
            bReg0 = *(const float4*)Wptr;
            bReg1 = *(const float4*)(Wptr + 4);
        }
        #pragma unroll
        for (int kk = 0; kk < 8; kk++) {
            float4 t0 = *(const float4*)&As[kk][ty * 8];
            float4 t1 = *(const float4*)&As[kk][ty * 8 + 4];
            u64 ra[8] = { pk2(t0.x, t0.x), pk2(t0.y, t0.y), pk2(t0.z, t0.z), pk2(t0.w, t0.w),
                          pk2(t1.x, t1.x), pk2(t1.y, t1.y), pk2(t1.z, t1.z), pk2(t1.w, t1.w) };
            u64 rb[8];
            #pragma unroll
            for (int j = 0; j < 8; j++) {
                float2 bv = *(const float2*)&Bs[kk][2 * tx + 32 * j];
                rb[j] = pk2(bv.x, bv.y);
            }
            #pragma unroll
            for (int i = 0; i < 8; i++)
                #pragma unroll
                for (int j = 0; j < 8; j++)
                    acc[i][j] = ffma2(ra[i], rb[j], acc[i][j]);
        }
        __syncthreads();
    }
    #pragma unroll
    for (int i = 0; i < 8; i++) {
        int r = rowStart + ty * 8 + i;
        float* Crow = C + (size_t)r * 768 + colStart;
        #pragma unroll
        for (int j = 0; j < 8; j++) {
            int c = 2 * tx + 32 * j;
            float lo, hi;
            upk2(acc[i][j], lo, hi);
            lo += bias[colStart + c];
            hi += bias[colStart + c + 1];
            *(float2*)(Crow + c) = make_float2(lo, hi);
        }
    }
}

// ---------------- scores = 8 * Q @ K^T per (b,h). 128x256 tiles, BK=8, f32x2 ----------------
__global__ void __launch_bounds__(256) score2_kernel(
    const float* __restrict__ Q, const float* __restrict__ Kmat,
    float* __restrict__ Sc, int H, int hd)
{
    const int bh = blockIdx.z;
    const int b = bh / H, h = bh - b * H;
    const float* A = Q + (size_t)b * SS * DM + h * hd;
    const float* Bm = Kmat + (size_t)b * SS * DM + h * hd;
    float* C = Sc + (size_t)bh * SS * SS;

    __shared__ float As[8][128];
    __shared__ float Bs[8][256];
    const int tid = threadIdx.x;
    const int rowStart = blockIdx.y * 128, colStart = blockIdx.x * 256;
    const int tx = tid & 15, ty = tid >> 4;
    const int aRow = tid >> 1, aCol = (tid & 1) * 4;
    const float* Aptr = A + (size_t)(rowStart + aRow) * DM + aCol;
    const float* Bptr = Bm + (size_t)(colStart + tid) * DM;   // thread owns one key row

    u64 acc[8][8];
    #pragma unroll
    for (int i = 0; i < 8; i++)
        #pragma unroll
        for (int j = 0; j < 8; j++) acc[i][j] = 0ull;

    float4 aReg = *(const float4*)Aptr;
    float4 bReg0 = *(const float4*)Bptr;
    float4 bReg1 = *(const float4*)(Bptr + 4);

    for (int k0 = 0; k0 < hd; k0 += 8) {
        As[aCol + 0][aRow] = aReg.x;
        As[aCol + 1][aRow] = aReg.y;
        As[aCol + 2][aRow] = aReg.z;
        As[aCol + 3][aRow] = aReg.w;
        Bs[0][tid] = bReg0.x; Bs[1][tid] = bReg0.y; Bs[2][tid] = bReg0.z; Bs[3][tid] = bReg0.w;
        Bs[4][tid] = bReg1.x; Bs[5][tid] = bReg1.y; Bs[6][tid] = bReg1.z; Bs[7][tid] = bReg1.w;
        __syncthreads();
        if (k0 + 8 < hd) {
            Aptr += 8;
            aReg = *(const float4*)Aptr;
            bReg0 = *(const float4*)(Bptr + k0 + 8);
            bReg1 = *(const float4*)(Bptr + k0 + 12);
        }
        #pragma unroll
        for (int kk = 0; kk < 8; kk++) {
            float4 t0 = *(const float4*)&As[kk][ty * 8];
            float4 t1 = *(const float4*)&As[kk][ty * 8 + 4];
            u64 ra[8] = { pk2(t0.x, t0.x), pk2(t0.y, t0.y), pk2(t0.z, t0.z), pk2(t0.w, t0.w),
                          pk2(t1.x, t1.x), pk2(t1.y, t1.y), pk2(t1.z, t1.z), pk2(t1.w, t1.w) };
            u64 rb[8];
            #pragma unroll
            for (int j = 0; j < 8; j++) {
                float2 bv = *(const float2*)&Bs[kk][2 * tx + 32 * j];
                rb[j] = pk2(bv.x, bv.y);
            }
            #pragma unroll
            for (int i = 0; i < 8; i++)
                #pragma unroll
                for (int j = 0; j < 8; j++)
                    acc[i][j] = ffma2(ra[i], rb[j], acc[i][j]);
        }
        __syncthreads();
    }
    #pragma unroll
    for (int i = 0; i < 8; i++) {
        int r = rowStart + ty * 8 + i;
        float* Crow = C + (size_t)r * SS + colStart;
        #pragma unroll
        for (int j = 0; j < 8; j++) {
            int c = 2 * tx + 32 * j;
            float lo, hi;
            upk2(acc[i][j], lo, hi);
            *(float2*)(Crow + c) = make_float2(8.f * lo, 8.f * hi);
        }
    }
}

// ---------------- out_head = P @ V_head per (b,h). 128x96 tiles, BK=8, f32x2 ----------------
__global__ void __launch_bounds__(256) pv_kernel(
    const float* __restrict__ P, const float* __restrict__ V,
    float* __restrict__ Out, int H, int hd)
{
    const int bh = blockIdx.z;
    const int b = bh / H, h = bh - b * H;
    const float* Pp = P + (size_t)bh * SS * SS;
    const float* Vp = V + (size_t)b * SS * DM + h * hd;

    __shared__ float Ps[8][128];
    __shared__ float Vs[8][96];
    const int tid = threadIdx.x;
    const int rowStart = blockIdx.y * 128, colStart = blockIdx.x * 96;
    const int tx = tid & 15, ty = tid >> 4;
    const int aRow = tid >> 1, aCol = (tid & 1) * 4;
    const float* Aptr = Pp + (size_t)(rowStart + aRow) * SS + aCol;
    const int vRow = tid / 24, vCol = (tid % 24) * 4;   // 192 active threads

    u64 acc[8][3];
    #pragma unroll
    for (int i = 0; i < 8; i++)
        #pragma unroll
        for (int j = 0; j < 3; j++) acc[i][j] = 0ull;

    for (int k0 = 0; k0 < SS; k0 += 8) {
        float4 av = *(const float4*)Aptr;
        Ps[aCol + 0][aRow] = av.x;
        Ps[aCol + 1][aRow] = av.y;
        Ps[aCol + 2][aRow] = av.z;
        Ps[aCol + 3][aRow] = av.w;
        if (tid < 192) {
            float4 vv = *(const float4*)(Vp + (size_t)(k0 + vRow) * DM + colStart + vCol);
            *(float4*)&Vs[vRow][vCol] = vv;
        }
        __syncthreads();
        #pragma unroll
        for (int kk = 0; kk < 8; kk++) {
            float4 t0 = *(const float4*)&Ps[kk][ty * 8];
            float4 t1 = *(const float4*)&Ps[kk][ty * 8 + 4];
            u64 ra[8] = { pk2(t0.x, t0.x), pk2(t0.y, t0.y), pk2(t0.z, t0.z), pk2(t0.w, t0.w),
                          pk2(t1.x, t1.x), pk2(t1.y, t1.y), pk2(t1.z, t1.z), pk2(t1.w, t1.w) };
            u64 rb[3];
            #pragma unroll
            for (int j = 0; j < 3; j++) {
                float2 bv = *(const float2*)&Vs[kk][tx * 6 + 2 * j];
                rb[j] = pk2(bv.x, bv.y);
            }
            #pragma unroll
            for (int i = 0; i < 8; i++)
                #pragma unroll
                for (int j = 0; j < 3; j++)
                    acc[i][j] = ffma2(ra[i], rb[j], acc[i][j]);
        }
        __syncthreads();
        Aptr += 8;
    }
    #pragma unroll
    for (int i = 0; i < 8; i++) {
        int r = rowStart + ty * 8 + i;
        float* Orow = Out + ((size_t)b * SS + r) * DM + h * hd + colStart;
        #pragma unroll
        for (int j = 0; j < 3; j++) {
            int c = tx * 6 + 2 * j;
            float lo, hi;
            upk2(acc[i][j], lo, hi);
            *(float2*)(Orow + c) = make_float2(lo, hi);
        }
    }
}

// ---------------- host ----------------

extern "C" void kernel_launch(void* const* d_in, const int* in_sizes, int n_in,
                              void* d_out, int out_size)
{
    (void)n_in; (void)out_size;
    const float *text, *vtab, *atab;
    const float *aw[18];  // hv(wq,bq,wk,bk,wv,bv), ha(...), ht(...)
    const float *fcw, *fcb, *f1w, *f1b, *f2w, *f2b, *catw, *catb;
    const int *vid, *aid;

    if (in_sizes[1] == MR) {
        // setup_inputs() dict order
        text = (const float*)d_in[0];
        vid  = (const int*)d_in[1];
        aid  = (const int*)d_in[2];
        vtab = (const float*)d_in[3];
        atab = (const float*)d_in[4];
        for (int i = 0; i < 18; i++) aw[i] = (const float*)d_in[5 + i];
        fcw = (const float*)d_in[23]; fcb = (const float*)d_in[24];
        f1w = (const float*)d_in[25]; f1b = (const float*)d_in[26];
        f2w = (const float*)d_in[27]; f2b = (const float*)d_in[28];
        catw = (const float*)d_in[29]; catb = (const float*)d_in[30];
    } else {
        // reference() signature order
        text = (const float*)d_in[0];
        vtab = (const float*)d_in[1];
        atab = (const float*)d_in[2];
        for (int i = 0; i < 18; i++) aw[i] = (const float*)d_in[3 + i];
        fcw = (const float*)d_in[21]; fcb = (const float*)d_in[22];
        f1w = (const float*)d_in[23]; f1b = (const float*)d_in[24];
        f2w = (const float*)d_in[25]; f2b = (const float*)d_in[26];
        catw = (const float*)d_in[27]; catb = (const float*)d_in[28];
        vid  = (const int*)d_in[29];
        aid  = (const int*)d_in[30];
    }

    float *embv, *emba, *q, *k, *v, *vatt, *aatt, *v2, *a2, *F1, *F2, *F3, *t1, *t2, *sc;
    cudaGetSymbolAddress((void**)&embv, g_embv);
    cudaGetSymbolAddress((void**)&emba, g_emba);
    cudaGetSymbolAddress((void**)&q, g_q);
    cudaGetSymbolAddress((void**)&k, g_k);
    cudaGetSymbolAddress((void**)&v, g_v);
    cudaGetSymbolAddress((void**)&vatt, g_vatt);
    cudaGetSymbolAddress((void**)&aatt, g_aatt);
    cudaGetSymbolAddress((void**)&v2, g_v2);
    cudaGetSymbolAddress((void**)&a2, g_a2);
    cudaGetSymbolAddress((void**)&F1, g_F1);
    cudaGetSymbolAddress((void**)&F2, g_F2);
    cudaGetSymbolAddress((void**)&F3, g_F3);
    cudaGetSymbolAddress((void**)&t1, g_t1);
    cudaGetSymbolAddress((void**)&t2, g_t2);
    cudaGetSymbolAddress((void**)&sc, g_scores);

    const dim3 gGemm(3, 128);       // N=768/256, M=16384/128
    const int EW = (NEL + 255) / 256;
    const int RW = (MR * (DM / 2) + 255) / 256;

    auto GEMM = [&](const float* A, const float* Wm, const float* bi, float* Cc) {
        sgemm2_kernel<0><<<gGemm, 256>>>(A, Wm, bi, Cc, 768, 768);
    };
    auto ROPE = [&](float* x) { rope_kernel<<<RW, 256>>>(x); };
    auto ATT1 = [&](const float* qin, const float* kvin, const float* const* w6, float* outb) {
        GEMM(qin, w6[0], w6[1], q);  ROPE(q);
        GEMM(kvin, w6[2], w6[3], k); ROPE(k);
        GEMM(kvin, w6[4], w6[5], v);
        score2_kernel<<<dim3(2, 4, 32), 256>>>(q, k, sc, 1, 768);
        softmax512_kernel<<<BB * SS, 256>>>(sc);
        pv_kernel<<<dim3(8, 4, 32), 256>>>(sc, v, outb, 1, 768);
    };
    auto FFN = [&](float* x) {  // x = ffn(gate(x))
        gate_kernel<<<MR, 256>>>(x, t1);
        sgemm2_kernel<1><<<gGemm, 256>>>(t1, f1w, f1b, t2, 768, 768);
        sgemm2_kernel<0><<<gGemm, 256>>>(t2, f2w, f2b, x, 768, 768);
    };

    // embeddings
    embed_kernel<<<EW, 256>>>(vtab, vid, embv);
    embed_kernel<<<EW, 256>>>(atab, aid, emba);

    // stage 1: visual_ = hv(text, emb_v); acoustic_ = ha(text, emb_a)
    ATT1(text, embv, &aw[0], vatt);
    ATT1(text, emba, &aw[6], aatt);

    // F1 = ffn(gate(cat(visual_, acoustic_) @ cat_w + b))
    sgemm2_cat_kernel<<<gGemm, 256>>>(vatt, aatt, catw, catb, F1);
    FFN(F1);

    // stage 2: v = hv(visual_, acoustic_); a = ha(acoustic_, visual_)
    ATT1(vatt, aatt, &aw[0], v2);
    ATT1(aatt, vatt, &aw[6], a2);
    sgemm2_cat_kernel<<<gGemm, 256>>>(v2, a2, catw, catb, F2);
    FFN(F2);

    // stage 3: F3 = mh8(F1, text) @ fcw + fcb, then ffn(gate(...))
    GEMM(F1, aw[12], aw[13], q);  ROPE(q);
    GEMM(text, aw[14], aw[15], k); ROPE(k);
    GEMM(text, aw[16], aw[17], v);
    score2_kernel<<<dim3(2, 4, 256), 256>>>(q, k, sc, 8, 96);
    softmax512_kernel<<<BB * 8 * SS, 256>>>(sc);
    pv_kernel<<<dim3(1, 4, 256), 256>>>(sc, v, t1, 8, 96);
    GEMM(t1, fcw, fcb, F3);
    FFN(F3);

    // es = text + F1 + F2 + F3; out = gate(es)
    add4_kernel<<<EW, 256>>>(text, F1, F2, F3, t1);
    gate_kernel<<<MR, 256>>>(t1, (float*)d_out);
}

// round 5
// speedup vs baseline: 2.8834x; 1.4819x over previous
#include <cuda_runtime.h>
#include <cuda_bf16.h>
#include <math.h>
#include <stdint.h>

#define DM 768
#define BB 32
#define SS 512
#define MR (BB*SS)          // 16384 rows
#define NEL (MR*DM)         // 12582912 elements per [B,S,D] tensor

typedef unsigned long long u64;
typedef __nv_bfloat16 bf16;

// ======================= helpers =======================
__device__ __forceinline__ u64 pk2(float lo, float hi) {
    u64 r; asm("mov.b64 %0,{%1,%2};" : "=l"(r) : "f"(lo), "f"(hi)); return r;
}
__device__ __forceinline__ void upk2(u64 v, float& lo, float& hi) {
    asm("mov.b64 {%0,%1},%2;" : "=f"(lo), "=f"(hi) : "l"(v));
}
__device__ __forceinline__ u64 ffma2(u64 a, u64 b, u64 c) {
    u64 d; asm("fma.rn.f32x2 %0,%1,%2,%3;" : "=l"(d) : "l"(a), "l"(b), "l"(c)); return d;
}
__device__ __forceinline__ uint32_t smem_u32(const void* p) {
    uint32_t a;
    asm("{ .reg .u64 t; cvta.to.shared.u64 t, %1; cvt.u32.u64 %0, t; }" : "=r"(a) : "l"(p));
    return a;
}
__device__ __forceinline__ void cp_async16(uint32_t dst, const void* src) {
    asm volatile("cp.async.cg.shared.global [%0],[%1],16;" :: "r"(dst), "l"(src));
}
__device__ __forceinline__ void cp_commit() {
    asm volatile("cp.async.commit_group;");
}
template <int N>
__device__ __forceinline__ void cp_wait() {
    asm volatile("cp.async.wait_group %0;" :: "n"(N));
}
__device__ __forceinline__ void ldmx4(uint32_t& a0, uint32_t& a1, uint32_t& a2, uint32_t& a3, uint32_t addr) {
    asm volatile("ldmatrix.sync.aligned.m8n8.x4.shared.b16 {%0,%1,%2,%3},[%4];"
                 : "=r"(a0), "=r"(a1), "=r"(a2), "=r"(a3) : "r"(addr));
}
__device__ __forceinline__ void ldmx2(uint32_t& b0, uint32_t& b1, uint32_t addr) {
    asm volatile("ldmatrix.sync.aligned.m8n8.x2.shared.b16 {%0,%1},[%2];"
                 : "=r"(b0), "=r"(b1) : "r"(addr));
}
__device__ __forceinline__ void mma16816(float* c, uint32_t a0, uint32_t a1, uint32_t a2, uint32_t a3,
                                         uint32_t b0, uint32_t b1) {
    asm volatile("mma.sync.aligned.m16n8k16.row.col.f32.bf16.bf16.f32 "
                 "{%0,%1,%2,%3},{%4,%5,%6,%7},{%8,%9},{%0,%1,%2,%3};"
                 : "+f"(c[0]), "+f"(c[1]), "+f"(c[2]), "+f"(c[3])
                 : "r"(a0), "r"(a1), "r"(a2), "r"(a3), "r"(b0), "r"(b1));
}
// swizzled chunk offset within a 128row x 64B tile
__device__ __forceinline__ uint32_t swz(int row, int chunk) {
    return (uint32_t)(row * 64 + ((chunk ^ ((row >> 1) & 3)) << 4));
}

// ======================= scratch =======================
static __device__ float g_embv[NEL];
static __device__ float g_emba[NEL];
static __device__ float g_q[NEL];
static __device__ float g_k[NEL];
static __device__ float g_v[NEL];
static __device__ float g_vatt[NEL];
static __device__ float g_aatt[NEL];
static __device__ float g_v2[NEL];
static __device__ float g_a2[NEL];
static __device__ float g_F1[NEL];
static __device__ float g_F2[NEL];
static __device__ float g_F3[NEL];
static __device__ float g_t1[NEL];
static __device__ float g_t2[NEL];
static __device__ float g_scores[67108864];   // 256 MB

#define WSZ (768*768)
static __device__ bf16 g_wth[12 * WSZ];   // transposed hi weights [N=768,K] x12
static __device__ bf16 g_wtl[12 * WSZ];
static __device__ bf16 g_cth[768 * 1536];
static __device__ bf16 g_ctl[768 * 1536];

static __device__ bf16 g_spt_h[NEL], g_spt_l[NEL];
static __device__ bf16 g_spa_h[NEL], g_spa_l[NEL];
static __device__ bf16 g_spb_h[NEL], g_spb_l[NEL];
static __device__ bf16 g_spc_h[NEL], g_spc_l[NEL];

// ======================= elementwise =======================
__global__ void __launch_bounds__(256) embed_kernel(
    const float* __restrict__ tab, const int* __restrict__ ids, float* __restrict__ out)
{
    int i = blockIdx.x * 256 + threadIdx.x;
    if (i >= NEL) return;
    int row = i / DM;
    int d = i - row * DM;
    out[i] = tab[(size_t)ids[row] * DM + d];
}

__global__ void __launch_bounds__(256) rope_kernel(float* __restrict__ x)
{
    int i = blockIdx.x * 256 + threadIdx.x;
    if (i >= MR * (DM / 2)) return;
    int row = i / (DM / 2);
    int j = i - row * (DM / 2);
    int s = row & (SS - 1);
    const float coef = -0.034603417655075f; // -2*log2(10000)/768
    float theta = exp2f(coef * (float)j);
    float ang = (float)s * theta;
    float sn, c;
    sincosf(ang, &sn, &c);
    float* p = x + (size_t)row * DM + 2 * j;
    float x0 = p[0], x1 = p[1];
    p[0] = x0 * c - x1 * sn;
    p[1] = x1 * c + x0 * sn;
}

__global__ void __launch_bounds__(256) add4_kernel(
    const float* __restrict__ a, const float* __restrict__ b,
    const float* __restrict__ c, const float* __restrict__ d, float* __restrict__ o)
{
    int i = blockIdx.x * 256 + threadIdx.x;
    if (i < NEL) o[i] = a[i] + b[i] + c[i] + d[i];
}

__global__ void __launch_bounds__(256) asplit_kernel(
    const float* __restrict__ x, bf16* __restrict__ h, bf16* __restrict__ l)
{
    int i = blockIdx.x * 256 + threadIdx.x;
    if (i >= NEL / 2) return;
    float2 v = ((const float2*)x)[i];
    bf16 h0 = __float2bfloat16(v.x);
    bf16 h1 = __float2bfloat16(v.y);
    __nv_bfloat162 hh; hh.x = h0; hh.y = h1;
    __nv_bfloat162 ll;
    ll.x = __float2bfloat16(v.x - __bfloat162float(h0));
    ll.y = __float2bfloat16(v.y - __bfloat162float(h1));
    ((__nv_bfloat162*)h)[i] = hh;
    ((__nv_bfloat162*)l)[i] = ll;
}

// transpose + split: W [K,768] -> T_hi/lo [768,K]
__global__ void __launch_bounds__(256) wsplit_kernel(
    const float* __restrict__ W, bf16* __restrict__ Th, bf16* __restrict__ Tl, int K)
{
    __shared__ float t[32][33];
    int k0 = blockIdx.x * 32, n0 = blockIdx.y * 32;
    int tx = threadIdx.x & 31, ty = threadIdx.x >> 5;
    #pragma unroll
    for (int i = 0; i < 32; i += 8)
        t[ty + i][tx] = W[(size_t)(k0 + ty + i) * 768 + n0 + tx];
    __syncthreads();
    #pragma unroll
    for (int i = 0; i < 32; i += 8) {
        float x = t[tx][ty + i];
        bf16 h = __float2bfloat16(x);
        bf16 l = __float2bfloat16(x - __bfloat162float(h));
        size_t o = (size_t)(n0 + ty + i) * K + k0 + tx;
        Th[o] = h; Tl[o] = l;
    }
}

__global__ void __launch_bounds__(256) softmax512_kernel(float* __restrict__ x)
{
    __shared__ float shm[8];
    __shared__ float shs[8];
    size_t row = blockIdx.x;
    float* p = x + row * 512;
    int t = threadIdx.x;
    int lane = t & 31, wid = t >> 5;

    float a = p[t], b = p[t + 256];
    float m = fmaxf(a, b);
    #pragma unroll
    for (int o = 16; o; o >>= 1) m = fmaxf(m, __shfl_xor_sync(0xffffffffu, m, o));
    if (lane == 0) shm[wid] = m;
    __syncthreads();
    float m2 = shm[0];
    #pragma unroll
    for (int i = 1; i < 8; i++) m2 = fmaxf(m2, shm[i]);

    float e0 = __expf(a - m2), e1 = __expf(b - m2);
    float s = e0 + e1;
    #pragma unroll
    for (int o = 16; o; o >>= 1) s += __shfl_xor_sync(0xffffffffu, s, o);
    if (lane == 0) shs[wid] = s;
    __syncthreads();
    float s2 = 0.f;
    #pragma unroll
    for (int i = 0; i < 8; i++) s2 += shs[i];
    float inv = 1.f / s2;
    p[t] = e0 * inv;
    p[t + 256] = e1 * inv;
}

__global__ void __launch_bounds__(256) gate_kernel(
    const float* __restrict__ in, float* __restrict__ out)
{
    __shared__ float shm[8];
    __shared__ float shs[8];
    size_t row = blockIdx.x;
    const float* p = in + row * 768;
    float* q = out + row * 768;
    int t = threadIdx.x;
    int lane = t & 31, wid = t >> 5;

    float a = p[t], b = p[t + 256], c = p[t + 512];
    float m = fmaxf(fmaxf(a, b), c);
    #pragma unroll
    for (int o = 16; o; o >>= 1) m = fmaxf(m, __shfl_xor_sync(0xffffffffu, m, o));
    if (lane == 0) shm[wid] = m;
    __syncthreads();
    float m2 = shm[0];
    #pragma unroll
    for (int i = 1; i < 8; i++) m2 = fmaxf(m2, shm[i]);

    float e0 = __expf(a - m2), e1 = __expf(b - m2), e2 = __expf(c - m2);
    float s = e0 + e1 + e2;
    #pragma unroll
    for (int o = 16; o; o >>= 1) s += __shfl_xor_sync(0xffffffffu, s, o);
    if (lane == 0) shs[wid] = s;
    __syncthreads();
    float s2 = 0.f;
    #pragma unroll
    for (int i = 0; i < 8; i++) s2 += shs[i];
    float inv = 1.f / s2;
    q[t]       = a + a * e0 * inv;
    q[t + 256] = b + b * e1 * inv;
    q[t + 512] = c + c * e2 * inv;
}

// ======================= HMMA split-bf16 GEMM =======================
// C[M,768] = fp32(A) @ fp32(W) + bias via 3-product bf16 split.
// A hi/lo [M,K] row-major; W transposed hi/lo [768,K] row-major (n-major).
// 128x128 C tile, 8 warps (2x4), warp = 64x32, m16n8k16, cp.async double buffer, BK=32.
// SMEM per buffer: Ah, Al, Bh, Bl tiles of 128x32 bf16 (8KB each) = 32KB; x2 = 64KB.
#define HG_SMEM (2 * 4 * 8192)

template <int EPI, int CAT>
__global__ void __launch_bounds__(256, 1) hmma_gemm_kernel(
    const bf16* __restrict__ A1h, const bf16* __restrict__ A1l,
    const bf16* __restrict__ A2h, const bf16* __restrict__ A2l,
    const bf16* __restrict__ Wh, const bf16* __restrict__ Wl,
    const float* __restrict__ bias, float* __restrict__ C, int K)
{
    extern __shared__ char smem[];
    uint32_t sb = smem_u32(smem);
    const int tid = threadIdx.x;
    const int rowStart = blockIdx.y * 128, colStart = blockIdx.x * 128;
    const int warp = tid >> 5, lane = tid & 31;
    const int wm = (warp & 1) * 64, wn = (warp >> 1) * 32;

    // load assignment: thread -> row tid/2, chunks (tid&1)*2, +1  (chunk = 16B = 8 bf16)
    const int ldRow = tid >> 1;
    const int ldC0 = (tid & 1) * 2;
    const uint32_t so0 = swz(ldRow, ldC0);
    const uint32_t so1 = swz(ldRow, ldC0 + 1);

    float acc[4][4][4];
    #pragma unroll
    for (int i = 0; i < 4; i++)
        #pragma unroll
        for (int j = 0; j < 4; j++)
            #pragma unroll
            for (int c = 0; c < 4; c++) acc[i][j][c] = 0.f;

    const int NIT = K / 32;

    auto loadTile = [&](int buf, int k0) {
        uint32_t base = sb + buf * 32768;
        int kk = k0 + ldC0 * 8;
        const bf16 *ph, *pl; size_t aoff;
        if (!CAT) {
            ph = A1h; pl = A1l; aoff = (size_t)(rowStart + ldRow) * K + kk;
        } else if (k0 < 768) {
            ph = A1h; pl = A1l; aoff = (size_t)(rowStart + ldRow) * 768 + kk;
        } else {
            ph = A2h; pl = A2l; aoff = (size_t)(rowStart + ldRow) * 768 + (kk - 768);
        }
        cp_async16(base + so0, ph + aoff);
        cp_async16(base + so1, ph + aoff + 8);
        cp_async16(base + 8192 + so0, pl + aoff);
        cp_async16(base + 8192 + so1, pl + aoff + 8);
        size_t boff = (size_t)(colStart + ldRow) * K + kk;
        cp_async16(base + 16384 + so0, Wh + boff);
        cp_async16(base + 16384 + so1, Wh + boff + 8);
        cp_async16(base + 24576 + so0, Wl + boff);
        cp_async16(base + 24576 + so1, Wl + boff + 8);
    };

    // per-lane ldmatrix address components
    const int rA = lane & 15, khA = lane >> 4;
    const int rB = lane & 7, khB = (lane >> 3) & 1;

    auto compute = [&](int buf) {
        uint32_t tb = sb + buf * 32768;
        #pragma unroll
        for (int combo = 0; combo < 3; combo++) {
            uint32_t aBase = tb + ((combo == 2) ? 8192 : 0);
            uint32_t bBase = tb + ((combo == 1) ? 24576 : 16384);
            #pragma unroll
            for (int kc = 0; kc < 2; kc++) {
                uint32_t b0[4], b1[4];
                #pragma unroll
                for (int nf = 0; nf < 4; nf++) {
                    int r = wn + 8 * nf + rB;
                    uint32_t addr = bBase + (uint32_t)(r * 64 + (((kc * 2 + khB) ^ ((r >> 1) & 3)) << 4));
                    ldmx2(b0[nf], b1[nf], addr);
                }
                #pragma unroll
                for (int mf = 0; mf < 4; mf++) {
                    int r = wm + 16 * mf + rA;
                    uint32_t addr = aBase + (uint32_t)(r * 64 + (((kc * 2 + khA) ^ ((r >> 1) & 3)) << 4));
                    uint32_t a0, a1, a2, a3;
                    ldmx4(a0, a1, a2, a3, addr);
                    #pragma unroll
                    for (int nf = 0; nf < 4; nf++)
                        mma16816(acc[mf][nf], a0, a1, a2, a3, b0[nf], b1[nf]);
                }
            }
        }
    };

    loadTile(0, 0);
    cp_commit();
    for (int kt = 0; kt < NIT; kt++) {
        if (kt + 1 < NIT) {
            loadTile((kt + 1) & 1, (kt + 1) * 32);
            cp_commit();
            cp_wait<1>();
        } else {
            cp_wait<0>();
        }
        __syncthreads();
        compute(kt & 1);
        __syncthreads();
    }

    // epilogue
    const int g = lane >> 2, q4 = lane & 3;
    #pragma unroll
    for (int nf = 0; nf < 4; nf++) {
        int c = colStart + wn + 8 * nf + 2 * q4;
        float bx = bias[c], by = bias[c + 1];
        #pragma unroll
        for (int mf = 0; mf < 4; mf++) {
            int r0 = rowStart + wm + 16 * mf + g;
            float v0 = acc[mf][nf][0] + bx;
            float v1 = acc[mf][nf][1] + by;
            float v2 = acc[mf][nf][2] + bx;
            float v3 = acc[mf][nf][3] + by;
            if (EPI == 1) {
                v0 *= 1.f / (1.f + __expf(-v0));
                v1 *= 1.f / (1.f + __expf(-v1));
                v2 *= 1.f / (1.f + __expf(-v2));
                v3 *= 1.f / (1.f + __expf(-v3));
            }
            *(float2*)(C + (size_t)r0 * 768 + c) = make_float2(v0, v1);
            *(float2*)(C + (size_t)(r0 + 8) * 768 + c) = make_float2(v2, v3);
        }
    }
}

// ======================= f32x2 attention GEMMs =======================
__global__ void __launch_bounds__(256) score2_kernel(
    const float* __restrict__ Q, const float* __restrict__ Kmat,
    float* __restrict__ Sc, int H, int hd)
{
    const int bh = blockIdx.z;
    const int b = bh / H, h = bh - b * H;
    const float* A = Q + (size_t)b * SS * DM + h * hd;
    const float* Bm = Kmat + (size_t)b * SS * DM + h * hd;
    float* C = Sc + (size_t)bh * SS * SS;

    __shared__ float As[8][128];
    __shared__ float Bs[8][256];
    const int tid = threadIdx.x;
    const int rowStart = blockIdx.y * 128, colStart = blockIdx.x * 256;
    const int tx = tid & 15, ty = tid >> 4;
    const int aRow = tid >> 1, aCol = (tid & 1) * 4;
    const float* Aptr = A + (size_t)(rowStart + aRow) * DM + aCol;
    const float* Bptr = Bm + (size_t)(colStart + tid) * DM;

    u64 acc[8][8];
    #pragma unroll
    for (int i = 0; i < 8; i++)
        #pragma unroll
        for (int j = 0; j < 8; j++) acc[i][j] = 0ull;

    float4 aReg = *(const float4*)Aptr;
    float4 bReg0 = *(const float4*)Bptr;
    float4 bReg1 = *(const float4*)(Bptr + 4);

    for (int k0 = 0; k0 < hd; k0 += 8) {
        As[aCol + 0][aRow] = aReg.x;
        As[aCol + 1][aRow] = aReg.y;
        As[aCol + 2][aRow] = aReg.z;
        As[aCol + 3][aRow] = aReg.w;
        Bs[0][tid] = bReg0.x; Bs[1][tid] = bReg0.y; Bs[2][tid] = bReg0.z; Bs[3][tid] = bReg0.w;
        Bs[4][tid] = bReg1.x; Bs[5][tid] = bReg1.y; Bs[6][tid] = bReg1.z; Bs[7][tid] = bReg1.w;
        __syncthreads();
        if (k0 + 8 < hd) {
            Aptr += 8;
            aReg = *(const float4*)Aptr;
            bReg0 = *(const float4*)(Bptr + k0 + 8);
            bReg1 = *(const float4*)(Bptr + k0 + 12);
        }
        #pragma unroll
        for (int kk = 0; kk < 8; kk++) {
            float4 t0 = *(const float4*)&As[kk][ty * 8];
            float4 t1 = *(const float4*)&As[kk][ty * 8 + 4];
            u64 ra[8] = { pk2(t0.x, t0.x), pk2(t0.y, t0.y), pk2(t0.z, t0.z), pk2(t0.w, t0.w),
                          pk2(t1.x, t1.x), pk2(t1.y, t1.y), pk2(t1.z, t1.z), pk2(t1.w, t1.w) };
            u64 rb[8];
            #pragma unroll
            for (int j = 0; j < 8; j++) {
                float2 bv = *(const float2*)&Bs[kk][2 * tx + 32 * j];
                rb[j] = pk2(bv.x, bv.y);
            }
            #pragma unroll
            for (int i = 0; i < 8; i++)
                #pragma unroll
                for (int j = 0; j < 8; j++)
                    acc[i][j] = ffma2(ra[i], rb[j], acc[i][j]);
        }
        __syncthreads();
    }
    #pragma unroll
    for (int i = 0; i < 8; i++) {
        int r = rowStart + ty * 8 + i;
        float* Crow = C + (size_t)r * SS + colStart;
        #pragma unroll
        for (int j = 0; j < 8; j++) {
            int c = 2 * tx + 32 * j;
            float lo, hi;
            upk2(acc[i][j], lo, hi);
            *(float2*)(Crow + c) = make_float2(8.f * lo, 8.f * hi);
        }
    }
}

__global__ void __launch_bounds__(256) pv_kernel(
    const float* __restrict__ P, const float* __restrict__ V,
    float* __restrict__ Out, int H, int hd)
{
    const int bh = blockIdx.z;
    const int b = bh / H, h = bh - b * H;
    const float* Pp = P + (size_t)bh * SS * SS;
    const float* Vp = V + (size_t)b * SS * DM + h * hd;

    __shared__ float Ps[8][128];
    __shared__ float Vs[8][96];
    const int tid = threadIdx.x;
    const int rowStart = blockIdx.y * 128, colStart = blockIdx.x * 96;
    const int tx = tid & 15, ty = tid >> 4;
    const int aRow = tid >> 1, aCol = (tid & 1) * 4;
    const float* Aptr = Pp + (size_t)(rowStart + aRow) * SS + aCol;
    const int vRow = tid / 24, vCol = (tid % 24) * 4;

    u64 acc[8][3];
    #pragma unroll
    for (int i = 0; i < 8; i++)
        #pragma unroll
        for (int j = 0; j < 3; j++) acc[i][j] = 0ull;

    for (int k0 = 0; k0 < SS; k0 += 8) {
        float4 av = *(const float4*)Aptr;
        Ps[aCol + 0][aRow] = av.x;
        Ps[aCol + 1][aRow] = av.y;
        Ps[aCol + 2][aRow] = av.z;
        Ps[aCol + 3][aRow] = av.w;
        if (tid < 192) {
            float4 vv = *(const float4*)(Vp + (size_t)(k0 + vRow) * DM + colStart + vCol);
            *(float4*)&Vs[vRow][vCol] = vv;
        }
        __syncthreads();
        #pragma unroll
        for (int kk = 0; kk < 8; kk++) {
            float4 t0 = *(const float4*)&Ps[kk][ty * 8];
            float4 t1 = *(const float4*)&Ps[kk][ty * 8 + 4];
            u64 ra[8] = { pk2(t0.x, t0.x), pk2(t0.y, t0.y), pk2(t0.z, t0.z), pk2(t0.w, t0.w),
                          pk2(t1.x, t1.x), pk2(t1.y, t1.y), pk2(t1.z, t1.z), pk2(t1.w, t1.w) };
            u64 rb[3];
            #pragma unroll
            for (int j = 0; j < 3; j++) {
                float2 bv = *(const float2*)&Vs[kk][tx * 6 + 2 * j];
                rb[j] = pk2(bv.x, bv.y);
            }
            #pragma unroll
            for (int i = 0; i < 8; i++)
                #pragma unroll
                for (int j = 0; j < 3; j++)
                    acc[i][j] = ffma2(ra[i], rb[j], acc[i][j]);
        }
        __syncthreads();
        Aptr += 8;
    }
    #pragma unroll
    for (int i = 0; i < 8; i++) {
        int r = rowStart + ty * 8 + i;
        float* Orow = Out + ((size_t)b * SS + r) * DM + h * hd + colStart;
        #pragma unroll
        for (int j = 0; j < 3; j++) {
            int c = tx * 6 + 2 * j;
            float lo, hi;
            upk2(acc[i][j], lo, hi);
            *(float2*)(Orow + c) = make_float2(lo, hi);
        }
    }
}

// ======================= host =======================
extern "C" void kernel_launch(void* const* d_in, const int* in_sizes, int n_in,
                              void* d_out, int out_size)
{
    (void)n_in; (void)out_size;
    const float *text, *vtab, *atab;
    const float *aw[18];
    const float *fcw, *fcb, *f1w, *f1b, *f2w, *f2b, *catw, *catb;
    const int *vid, *aid;

    if (in_sizes[1] == MR) {
        text = (const float*)d_in[0];
        vid  = (const int*)d_in[1];
        aid  = (const int*)d_in[2];
        vtab = (const float*)d_in[3];
        atab = (const float*)d_in[4];
        for (int i = 0; i < 18; i++) aw[i] = (const float*)d_in[5 + i];
        fcw = (const float*)d_in[23]; fcb = (const float*)d_in[24];
        f1w = (const float*)d_in[25]; f1b = (const float*)d_in[26];
        f2w = (const float*)d_in[27]; f2b = (const float*)d_in[28];
        catw = (const float*)d_in[29]; catb = (const float*)d_in[30];
    } else {
        text = (const float*)d_in[0];
        vtab = (const float*)d_in[1];
        atab = (const float*)d_in[2];
        for (int i = 0; i < 18; i++) aw[i] = (const float*)d_in[3 + i];
        fcw = (const float*)d_in[21]; fcb = (const float*)d_in[22];
        f1w = (const float*)d_in[23]; f1b = (const float*)d_in[24];
        f2w = (const float*)d_in[25]; f2b = (const float*)d_in[26];
        catw = (const float*)d_in[27]; catb = (const float*)d_in[28];
        vid  = (const int*)d_in[29];
        aid  = (const int*)d_in[30];
    }

    cudaFuncSetAttribute(hmma_gemm_kernel<0,0>, cudaFuncAttributeMaxDynamicSharedMemorySize, HG_SMEM);
    cudaFuncSetAttribute(hmma_gemm_kernel<1,0>, cudaFuncAttributeMaxDynamicSharedMemorySize, HG_SMEM);
    cudaFuncSetAttribute(hmma_gemm_kernel<0,1>, cudaFuncAttributeMaxDynamicSharedMemorySize, HG_SMEM);

    float *embv, *emba, *q, *k, *v, *vatt, *aatt, *v2, *a2, *F1, *F2, *F3, *t1, *t2, *sc;
    bf16 *wth, *wtl, *cth, *ctl;
    bf16 *spt_h, *spt_l, *spa_h, *spa_l, *spb_h, *spb_l, *spc_h, *spc_l;
    cudaGetSymbolAddress((void**)&embv, g_embv);
    cudaGetSymbolAddress((void**)&emba, g_emba);
    cudaGetSymbolAddress((void**)&q, g_q);
    cudaGetSymbolAddress((void**)&k, g_k);
    cudaGetSymbolAddress((void**)&v, g_v);
    cudaGetSymbolAddress((void**)&vatt, g_vatt);
    cudaGetSymbolAddress((void**)&aatt, g_aatt);
    cudaGetSymbolAddress((void**)&v2, g_v2);
    cudaGetSymbolAddress((void**)&a2, g_a2);
    cudaGetSymbolAddress((void**)&F1, g_F1);
    cudaGetSymbolAddress((void**)&F2, g_F2);
    cudaGetSymbolAddress((void**)&F3, g_F3);
    cudaGetSymbolAddress((void**)&t1, g_t1);
    cudaGetSymbolAddress((void**)&t2, g_t2);
    cudaGetSymbolAddress((void**)&sc, g_scores);
    cudaGetSymbolAddress((void**)&wth, g_wth);
    cudaGetSymbolAddress((void**)&wtl, g_wtl);
    cudaGetSymbolAddress((void**)&cth, g_cth);
    cudaGetSymbolAddress((void**)&ctl, g_ctl);
    cudaGetSymbolAddress((void**)&spt_h, g_spt_h);
    cudaGetSymbolAddress((void**)&spt_l, g_spt_l);
    cudaGetSymbolAddress((void**)&spa_h, g_spa_h);
    cudaGetSymbolAddress((void**)&spa_l, g_spa_l);
    cudaGetSymbolAddress((void**)&spb_h, g_spb_h);
    cudaGetSymbolAddress((void**)&spb_l, g_spb_l);
    cudaGetSymbolAddress((void**)&spc_h, g_spc_h);
    cudaGetSymbolAddress((void**)&spc_l, g_spc_l);

    const int EW = (NEL + 255) / 256;
    const int RW = (MR * (DM / 2) + 255) / 256;
    const int SW = (NEL / 2 + 255) / 256;
    const dim3 gHG(6, 128);

    // -------- weight prep: transpose + bf16 split --------
    const float* wsrc[12] = { aw[0], aw[2], aw[4], aw[6], aw[8], aw[10],
                              aw[12], aw[14], aw[16], fcw, f1w, f2w };
    for (int i = 0; i < 12; i++)
        wsplit_kernel<<<dim3(24, 24), 256>>>(wsrc[i], wth + (size_t)i * WSZ, wtl + (size_t)i * WSZ, 768);
    wsplit_kernel<<<dim3(48, 24), 256>>>(catw, cth, ctl, 1536);

    auto SPLIT = [&](const float* x, bf16* h, bf16* l) {
        asplit_kernel<<<SW, 256>>>(x, h, l);
    };
    auto TGEMM = [&](const bf16* Ah, const bf16* Al, int wi, const float* bi, float* Cc, int epi) {
        const bf16* Wh = wth + (size_t)wi * WSZ;
        const bf16* Wl = wtl + (size_t)wi * WSZ;
        if (epi) hmma_gemm_kernel<1,0><<<gHG, 256, HG_SMEM>>>(Ah, Al, nullptr, nullptr, Wh, Wl, bi, Cc, 768);
        else     hmma_gemm_kernel<0,0><<<gHG, 256, HG_SMEM>>>(Ah, Al, nullptr, nullptr, Wh, Wl, bi, Cc, 768);
    };
    auto CATGEMM = [&](const bf16* A1h, const bf16* A1l, const bf16* A2h, const bf16* A2l,
                       const float* bi, float* Cc) {
        hmma_gemm_kernel<0,1><<<gHG, 256, HG_SMEM>>>(A1h, A1l, A2h, A2l, cth, ctl, bi, Cc, 1536);
    };
    auto ROPE = [&](float* x) { rope_kernel<<<RW, 256>>>(x); };
    auto ATT1 = [&](const bf16* qh, const bf16* ql, const bf16* kvh, const bf16* kvl,
                    int wbase, const float* const* wb6, float* outb) {
        TGEMM(qh, ql, wbase + 0, wb6[1], q, 0);  ROPE(q);
        TGEMM(kvh, kvl, wbase + 1, wb6[3], k, 0); ROPE(k);
        TGEMM(kvh, kvl, wbase + 2, wb6[5], v, 0);
        score2_kernel<<<dim3(2, 4, 32), 256>>>(q, k, sc, 1, 768);
        softmax512_kernel<<<BB * SS, 256>>>(sc);
        pv_kernel<<<dim3(8, 4, 32), 256>>>(sc, v, outb, 1, 768);
    };
    auto FFN = [&](float* x) {
        gate_kernel<<<MR, 256>>>(x, t1);
        SPLIT(t1, spc_h, spc_l);
        TGEMM(spc_h, spc_l, 10, f1b, t2, 1);     // silu
        SPLIT(t2, spc_h, spc_l);
        TGEMM(spc_h, spc_l, 11, f2b, x, 0);
    };

    // -------- forward --------
    SPLIT(text, spt_h, spt_l);
    embed_kernel<<<EW, 256>>>(vtab, vid, embv);
    embed_kernel<<<EW, 256>>>(atab, aid, emba);
    SPLIT(embv, spa_h, spa_l);
    SPLIT(emba, spb_h, spb_l);

    // stage 1
    ATT1(spt_h, spt_l, spa_h, spa_l, 0, &aw[0], vatt);
    ATT1(spt_h, spt_l, spb_h, spb_l, 3, &aw[6], aatt);

    SPLIT(vatt, spa_h, spa_l);
    SPLIT(aatt, spb_h, spb_l);
    CATGEMM(spa_h, spa_l, spb_h, spb_l, catb, F1);
    FFN(F1);

    // stage 2 (spa = split(vatt), spb = split(aatt) still valid)
    ATT1(spa_h, spa_l, spb_h, spb_l, 0, &aw[0], v2);
    ATT1(spb_h, spb_l, spa_h, spa_l, 3, &aw[6], a2);
    SPLIT(v2, spa_h, spa_l);
    SPLIT(a2, spb_h, spb_l);
    CATGEMM(spa_h, spa_l, spb_h, spb_l, catb, F2);
    FFN(F2);

    // stage 3: F3 = mh8(F1, text) @ fcw + fcb
    SPLIT(F1, spa_h, spa_l);
    TGEMM(spa_h, spa_l, 6, aw[13], q, 0);  ROPE(q);
    TGEMM(spt_h, spt_l, 7, aw[15], k, 0);  ROPE(k);
    TGEMM(spt_h, spt_l, 8, aw[17], v, 0);
    score2_kernel<<<dim3(2, 4, 256), 256>>>(q, k, sc, 8, 96);
    softmax512_kernel<<<BB * 8 * SS, 256>>>(sc);
    pv_kernel<<<dim3(1, 4, 256), 256>>>(sc, v, t1, 8, 96);
    SPLIT(t1, spa_h, spa_l);
    TGEMM(spa_h, spa_l, 9, fcb, F3, 0);
    FFN(F3);

    // es = text + F1 + F2 + F3; out = gate(es)
    add4_kernel<<<EW, 256>>>(text, F1, F2, F3, t1);
    gate_kernel<<<MR, 256>>>(t1, (float*)d_out);
}

// round 6
// speedup vs baseline: 3.4593x; 1.1997x over previous
#include <cuda_runtime.h>
#include <cuda_bf16.h>
#include <math.h>
#include <stdint.h>

#define DM 768
#define BB 32
#define SS 512
#define MR (BB*SS)          // 16384 rows
#define NEL (MR*DM)         // 12582912

typedef __nv_bfloat16 bf16;

// ======================= helpers =======================
__device__ __forceinline__ uint32_t smem_u32(const void* p) {
    uint32_t a;
    asm("{ .reg .u64 t; cvta.to.shared.u64 t, %1; cvt.u32.u64 %0, t; }" : "=r"(a) : "l"(p));
    return a;
}
__device__ __forceinline__ void cp_async16(uint32_t dst, const void* src) {
    asm volatile("cp.async.cg.shared.global [%0],[%1],16;" :: "r"(dst), "l"(src));
}
__device__ __forceinline__ void cp_commit() { asm volatile("cp.async.commit_group;"); }
template <int N>
__device__ __forceinline__ void cp_wait() { asm volatile("cp.async.wait_group %0;" :: "n"(N)); }
__device__ __forceinline__ void ldmx4(uint32_t& a0, uint32_t& a1, uint32_t& a2, uint32_t& a3, uint32_t addr) {
    asm volatile("ldmatrix.sync.aligned.m8n8.x4.shared.b16 {%0,%1,%2,%3},[%4];"
                 : "=r"(a0), "=r"(a1), "=r"(a2), "=r"(a3) : "r"(addr));
}
__device__ __forceinline__ void ldmx2(uint32_t& b0, uint32_t& b1, uint32_t addr) {
    asm volatile("ldmatrix.sync.aligned.m8n8.x2.shared.b16 {%0,%1},[%2];"
                 : "=r"(b0), "=r"(b1) : "r"(addr));
}
__device__ __forceinline__ void mma16816(float* c, uint32_t a0, uint32_t a1, uint32_t a2, uint32_t a3,
                                         uint32_t b0, uint32_t b1) {
    asm volatile("mma.sync.aligned.m16n8k16.row.col.f32.bf16.bf16.f32 "
                 "{%0,%1,%2,%3},{%4,%5,%6,%7},{%8,%9},{%0,%1,%2,%3};"
                 : "+f"(c[0]), "+f"(c[1]), "+f"(c[2]), "+f"(c[3])
                 : "r"(a0), "r"(a1), "r"(a2), "r"(a3), "r"(b0), "r"(b1));
}
__device__ __forceinline__ uint32_t swz(int row, int chunk) {
    return (uint32_t)(row * 64 + ((chunk ^ ((row >> 1) & 3)) << 4));
}
// split a pair of floats into bf16 hi/lo and store packed
__device__ __forceinline__ void store_split2(bf16* Oh, bf16* Ol, size_t idx, float a, float b) {
    bf16 ha = __float2bfloat16(a);
    bf16 hb = __float2bfloat16(b);
    __nv_bfloat162 hh; hh.x = ha; hh.y = hb;
    __nv_bfloat162 ll;
    ll.x = __float2bfloat16(a - __bfloat162float(ha));
    ll.y = __float2bfloat16(b - __bfloat162float(hb));
    *(__nv_bfloat162*)(Oh + idx) = hh;
    *(__nv_bfloat162*)(Ol + idx) = ll;
}
__device__ __forceinline__ void split1(float x, bf16* h, bf16* l, size_t idx) {
    bf16 hh = __float2bfloat16(x);
    h[idx] = hh;
    l[idx] = __float2bfloat16(x - __bfloat162float(hh));
}

// ======================= scratch =======================
static __device__ float g_sc[67108864];     // fp32 scores 256MB
static __device__ float g_F1[NEL];
static __device__ float g_F2[NEL];
static __device__ float g_F3[NEL];
static __device__ float g_t1[NEL];

#define WSZ (768*768)
static __device__ bf16 g_wth[12 * WSZ];
static __device__ bf16 g_wtl[12 * WSZ];
static __device__ bf16 g_cth[768 * 1536];
static __device__ bf16 g_ctl[768 * 1536];

static __device__ bf16 g_spt_h[NEL], g_spt_l[NEL];     // text split
static __device__ bf16 g_sev_h[NEL], g_sev_l[NEL];     // embed visual
static __device__ bf16 g_sea_h[NEL], g_sea_l[NEL];     // embed acoustic
static __device__ bf16 g_sq_h[NEL],  g_sq_l[NEL];      // roped Q
static __device__ bf16 g_sk_h[NEL],  g_sk_l[NEL];      // roped K
static __device__ bf16 g_svt_h[NEL + 65536], g_svt_l[NEL + 65536];  // V^T (+pad)
static __device__ bf16 g_sp_h[67108864], g_sp_l[67108864];          // P split
static __device__ bf16 g_s1_h[NEL], g_s1_l[NEL];
static __device__ bf16 g_s2_h[NEL], g_s2_l[NEL];
static __device__ bf16 g_s3_h[NEL], g_s3_l[NEL];
static __device__ bf16 g_s4_h[NEL], g_s4_l[NEL];
static __device__ bf16 g_c1_h[NEL], g_c1_l[NEL];       // scratch splits
static __device__ bf16 g_c2_h[NEL], g_c2_l[NEL];

// ======================= elementwise =======================
__global__ void __launch_bounds__(256) embed_split_kernel(
    const float* __restrict__ tab, const int* __restrict__ ids,
    bf16* __restrict__ oh, bf16* __restrict__ ol)
{
    int i = blockIdx.x * 256 + threadIdx.x;
    if (i >= NEL) return;
    int row = i / DM;
    int d = i - row * DM;
    split1(tab[(size_t)ids[row] * DM + d], oh, ol, i);
}

__global__ void __launch_bounds__(256) asplit_kernel(
    const float* __restrict__ x, bf16* __restrict__ h, bf16* __restrict__ l)
{
    int i = blockIdx.x * 256 + threadIdx.x;
    if (i >= NEL / 2) return;
    float2 v = ((const float2*)x)[i];
    store_split2(h, l, (size_t)i * 2, v.x, v.y);
}

__global__ void __launch_bounds__(256) add4_kernel(
    const float* __restrict__ a, const float* __restrict__ b,
    const float* __restrict__ c, const float* __restrict__ d, float* __restrict__ o)
{
    int i = blockIdx.x * 256 + threadIdx.x;
    if (i < NEL) o[i] = a[i] + b[i] + c[i] + d[i];
}

// transpose + split: W [K,768] -> T_hi/lo [768,K]
__global__ void __launch_bounds__(256) wsplit_kernel(
    const float* __restrict__ W, bf16* __restrict__ Th, bf16* __restrict__ Tl, int K)
{
    __shared__ float t[32][33];
    int k0 = blockIdx.x * 32, n0 = blockIdx.y * 32;
    int tx = threadIdx.x & 31, ty = threadIdx.x >> 5;
    #pragma unroll
    for (int i = 0; i < 32; i += 8)
        t[ty + i][tx] = W[(size_t)(k0 + ty + i) * 768 + n0 + tx];
    __syncthreads();
    #pragma unroll
    for (int i = 0; i < 32; i += 8)
        split1(t[tx][ty + i], Th, Tl, (size_t)(n0 + ty + i) * K + k0 + tx);
}

// softmax over 512 + bf16 split output
__global__ void __launch_bounds__(256) softmax_split_kernel(
    const float* __restrict__ x, bf16* __restrict__ ph, bf16* __restrict__ pl)
{
    __shared__ float shm[8];
    __shared__ float shs[8];
    size_t row = blockIdx.x;
    const float* p = x + row * 512;
    int t = threadIdx.x;
    int lane = t & 31, wid = t >> 5;

    float a = p[t], b = p[t + 256];
    float m = fmaxf(a, b);
    #pragma unroll
    for (int o = 16; o; o >>= 1) m = fmaxf(m, __shfl_xor_sync(0xffffffffu, m, o));
    if (lane == 0) shm[wid] = m;
    __syncthreads();
    float m2 = shm[0];
    #pragma unroll
    for (int i = 1; i < 8; i++) m2 = fmaxf(m2, shm[i]);

    float e0 = __expf(a - m2), e1 = __expf(b - m2);
    float s = e0 + e1;
    #pragma unroll
    for (int o = 16; o; o >>= 1) s += __shfl_xor_sync(0xffffffffu, s, o);
    if (lane == 0) shs[wid] = s;
    __syncthreads();
    float s2 = 0.f;
    #pragma unroll
    for (int i = 0; i < 8; i++) s2 += shs[i];
    float inv = 1.f / s2;
    split1(e0 * inv, ph, pl, row * 512 + t);
    split1(e1 * inv, ph, pl, row * 512 + t + 256);
}

// gate: fp32 out (final)
__global__ void __launch_bounds__(256) gate_kernel(
    const float* __restrict__ in, float* __restrict__ out)
{
    __shared__ float shm[8];
    __shared__ float shs[8];
    size_t row = blockIdx.x;
    const float* p = in + row * 768;
    float* q = out + row * 768;
    int t = threadIdx.x;
    int lane = t & 31, wid = t >> 5;

    float a = p[t], b = p[t + 256], c = p[t + 512];
    float m = fmaxf(fmaxf(a, b), c);
    #pragma unroll
    for (int o = 16; o; o >>= 1) m = fmaxf(m, __shfl_xor_sync(0xffffffffu, m, o));
    if (lane == 0) shm[wid] = m;
    __syncthreads();
    float m2 = shm[0];
    #pragma unroll
    for (int i = 1; i < 8; i++) m2 = fmaxf(m2, shm[i]);

    float e0 = __expf(a - m2), e1 = __expf(b - m2), e2 = __expf(c - m2);
    float s = e0 + e1 + e2;
    #pragma unroll
    for (int o = 16; o; o >>= 1) s += __shfl_xor_sync(0xffffffffu, s, o);
    if (lane == 0) shs[wid] = s;
    __syncthreads();
    float s2 = 0.f;
    #pragma unroll
    for (int i = 0; i < 8; i++) s2 += shs[i];
    float inv = 1.f / s2;
    q[t]       = a + a * e0 * inv;
    q[t + 256] = b + b * e1 * inv;
    q[t + 512] = c + c * e2 * inv;
}

// gate with split output
__global__ void __launch_bounds__(256) gate_split_kernel(
    const float* __restrict__ in, bf16* __restrict__ oh, bf16* __restrict__ ol)
{
    __shared__ float shm[8];
    __shared__ float shs[8];
    size_t row = blockIdx.x;
    const float* p = in + row * 768;
    int t = threadIdx.x;
    int lane = t & 31, wid = t >> 5;

    float a = p[t], b = p[t + 256], c = p[t + 512];
    float m = fmaxf(fmaxf(a, b), c);
    #pragma unroll
    for (int o = 16; o; o >>= 1) m = fmaxf(m, __shfl_xor_sync(0xffffffffu, m, o));
    if (lane == 0) shm[wid] = m;
    __syncthreads();
    float m2 = shm[0];
    #pragma unroll
    for (int i = 1; i < 8; i++) m2 = fmaxf(m2, shm[i]);

    float e0 = __expf(a - m2), e1 = __expf(b - m2), e2 = __expf(c - m2);
    float s = e0 + e1 + e2;
    #pragma unroll
    for (int o = 16; o; o >>= 1) s += __shfl_xor_sync(0xffffffffu, s, o);
    if (lane == 0) shs[wid] = s;
    __syncthreads();
    float s2 = 0.f;
    #pragma unroll
    for (int i = 0; i < 8; i++) s2 += shs[i];
    float inv = 1.f / s2;
    split1(a + a * e0 * inv, oh, ol, row * 768 + t);
    split1(b + b * e1 * inv, oh, ol, row * 768 + t + 256);
    split1(c + c * e2 * inv, oh, ol, row * 768 + t + 512);
}

// ======================= HMMA core pieces =======================
#define HG_SMEM (2 * 4 * 8192)

// compute over one buffer: 3 combos (AhBh, AhBl, AlBh), 2 k-halves
#define HMMA_COMPUTE(tb)                                                             \
    _Pragma("unroll")                                                                \
    for (int combo = 0; combo < 3; combo++) {                                        \
        uint32_t aBase = (tb) + ((combo == 2) ? 8192 : 0);                           \
        uint32_t bBase = (tb) + ((combo == 1) ? 24576 : 16384);                      \
        _Pragma("unroll")                                                            \
        for (int kc = 0; kc < 2; kc++) {                                             \
            uint32_t b0[4], b1[4];                                                   \
            _Pragma("unroll")                                                        \
            for (int nf = 0; nf < 4; nf++) {                                         \
                int r = wn + 8 * nf + rB;                                            \
                uint32_t addr = bBase + (uint32_t)(r * 64 + (((kc * 2 + khB) ^ ((r >> 1) & 3)) << 4)); \
                ldmx2(b0[nf], b1[nf], addr);                                         \
            }                                                                        \
            _Pragma("unroll")                                                        \
            for (int mf = 0; mf < 4; mf++) {                                         \
                int r = wm + 16 * mf + rA;                                           \
                uint32_t addr = aBase + (uint32_t)(r * 64 + (((kc * 2 + khA) ^ ((r >> 1) & 3)) << 4)); \
                uint32_t a0, a1, a2, a3;                                             \
                ldmx4(a0, a1, a2, a3, addr);                                         \
                _Pragma("unroll")                                                    \
                for (int nf = 0; nf < 4; nf++)                                       \
                    mma16816(acc[mf][nf], a0, a1, a2, a3, b0[nf], b1[nf]);           \
            }                                                                        \
        }                                                                            \
    }

// ======================= projection GEMM =======================
// EPI: 0 = fp32+bias ; 2 = rope+split ; 4 = V-transpose+split ; 5 = silu+split
template <int EPI, int CAT>
__global__ void __launch_bounds__(256, 1) hmma_gemm_kernel(
    const bf16* __restrict__ A1h, const bf16* __restrict__ A1l,
    const bf16* __restrict__ A2h, const bf16* __restrict__ A2l,
    const bf16* __restrict__ Wh, const bf16* __restrict__ Wl,
    const float* __restrict__ bias, float* __restrict__ C,
    bf16* __restrict__ Oh, bf16* __restrict__ Ol, int K)
{
    extern __shared__ char smem[];
    uint32_t sb = smem_u32(smem);
    const int tid = threadIdx.x;
    const int rowStart = blockIdx.y * 128, colStart = blockIdx.x * 128;
    const int warp = tid >> 5, lane = tid & 31;
    const int wm = (warp & 1) * 64, wn = (warp >> 1) * 32;
    const int ldRow = tid >> 1;
    const int ldC0 = (tid & 1) * 2;
    const uint32_t so0 = swz(ldRow, ldC0);
    const uint32_t so1 = swz(ldRow, ldC0 + 1);

    float acc[4][4][4];
    #pragma unroll
    for (int i = 0; i < 4; i++)
        #pragma unroll
        for (int j = 0; j < 4; j++)
            #pragma unroll
            for (int c = 0; c < 4; c++) acc[i][j][c] = 0.f;

    const int NIT = K / 32;

    auto loadTile = [&](int buf, int k0) {
        uint32_t base = sb + buf * 32768;
        int kk = k0 + ldC0 * 8;
        const bf16 *ph, *pl; size_t aoff;
        if (!CAT) {
            ph = A1h; pl = A1l; aoff = (size_t)(rowStart + ldRow) * K + kk;
        } else if (k0 < 768) {
            ph = A1h; pl = A1l; aoff = (size_t)(rowStart + ldRow) * 768 + kk;
        } else {
            ph = A2h; pl = A2l; aoff = (size_t)(rowStart + ldRow) * 768 + (kk - 768);
        }
        cp_async16(base + so0, ph + aoff);
        cp_async16(base + so1, ph + aoff + 8);
        cp_async16(base + 8192 + so0, pl + aoff);
        cp_async16(base + 8192 + so1, pl + aoff + 8);
        size_t boff = (size_t)(colStart + ldRow) * K + kk;
        cp_async16(base + 16384 + so0, Wh + boff);
        cp_async16(base + 16384 + so1, Wh + boff + 8);
        cp_async16(base + 24576 + so0, Wl + boff);
        cp_async16(base + 24576 + so1, Wl + boff + 8);
    };

    const int rA = lane & 15, khA = lane >> 4;
    const int rB = lane & 7, khB = (lane >> 3) & 1;

    loadTile(0, 0);
    cp_commit();
    for (int kt = 0; kt < NIT; kt++) {
        if (kt + 1 < NIT) {
            loadTile((kt + 1) & 1, (kt + 1) * 32);
            cp_commit();
            cp_wait<1>();
        } else {
            cp_wait<0>();
        }
        __syncthreads();
        uint32_t tb = sb + (kt & 1) * 32768;
        HMMA_COMPUTE(tb)
        __syncthreads();
    }

    const int g = lane >> 2, q4 = lane & 3;
    const float coef = -0.034603417655075f; // -2*log2(10000)/768
    #pragma unroll
    for (int nf = 0; nf < 4; nf++) {
        int c = colStart + wn + 8 * nf + 2 * q4;
        float bx = bias[c], by = bias[c + 1];
        #pragma unroll
        for (int mf = 0; mf < 4; mf++) {
            int r0 = rowStart + wm + 16 * mf + g;
            float v0 = acc[mf][nf][0] + bx;
            float v1 = acc[mf][nf][1] + by;
            float v2 = acc[mf][nf][2] + bx;
            float v3 = acc[mf][nf][3] + by;
            if (EPI == 0) {
                *(float2*)(C + (size_t)r0 * 768 + c) = make_float2(v0, v1);
                *(float2*)(C + (size_t)(r0 + 8) * 768 + c) = make_float2(v2, v3);
            } else if (EPI == 2) {
                float theta = exp2f(coef * (float)(c >> 1));
                int s0 = r0 & (SS - 1);
                float sn, cs;
                sincosf((float)s0 * theta, &sn, &cs);
                float x0 = v0 * cs - v1 * sn, x1 = v1 * cs + v0 * sn;
                sincosf((float)(s0 + 8) * theta, &sn, &cs);
                float x2 = v2 * cs - v3 * sn, x3 = v3 * cs + v2 * sn;
                store_split2(Oh, Ol, (size_t)r0 * 768 + c, x0, x1);
                store_split2(Oh, Ol, (size_t)(r0 + 8) * 768 + c, x2, x3);
            } else if (EPI == 4) {
                int b = r0 >> 9, s0 = r0 & (SS - 1);
                split1(v0, Oh, Ol, ((size_t)(b * 768 + c)) * 512 + s0);
                split1(v1, Oh, Ol, ((size_t)(b * 768 + c + 1)) * 512 + s0);
                split1(v2, Oh, Ol, ((size_t)(b * 768 + c)) * 512 + s0 + 8);
                split1(v3, Oh, Ol, ((size_t)(b * 768 + c + 1)) * 512 + s0 + 8);
            } else { // EPI 5: silu + split
                v0 *= 1.f / (1.f + __expf(-v0));
                v1 *= 1.f / (1.f + __expf(-v1));
                v2 *= 1.f / (1.f + __expf(-v2));
                v3 *= 1.f / (1.f + __expf(-v3));
                store_split2(Oh, Ol, (size_t)r0 * 768 + c, v0, v1);
                store_split2(Oh, Ol, (size_t)(r0 + 8) * 768 + c, v2, v3);
            }
        }
    }
}

// ======================= attention score GEMM: Sc = 8 * Q @ K^T =======================
__global__ void __launch_bounds__(256, 1) hmma_score_kernel(
    const bf16* __restrict__ Qh, const bf16* __restrict__ Ql,
    const bf16* __restrict__ Kh, const bf16* __restrict__ Kl,
    float* __restrict__ Sc, int H, int hd)
{
    extern __shared__ char smem[];
    uint32_t sb = smem_u32(smem);
    const int tid = threadIdx.x;
    const int z = blockIdx.z, b = z / H, h = z - b * H;
    const int rowStart = blockIdx.y * 128, colStart = blockIdx.x * 128;
    const int warp = tid >> 5, lane = tid & 31;
    const int wm = (warp & 1) * 64, wn = (warp >> 1) * 32;
    const int ldRow = tid >> 1;
    const int ldC0 = (tid & 1) * 2;
    const uint32_t so0 = swz(ldRow, ldC0);
    const uint32_t so1 = swz(ldRow, ldC0 + 1);

    float acc[4][4][4];
    #pragma unroll
    for (int i = 0; i < 4; i++)
        #pragma unroll
        for (int j = 0; j < 4; j++)
            #pragma unroll
            for (int c = 0; c < 4; c++) acc[i][j][c] = 0.f;

    const int NIT = hd / 32;

    auto loadTile = [&](int buf, int k0) {
        uint32_t base = sb + buf * 32768;
        int kk = k0 + ldC0 * 8;
        size_t aoff = (size_t)(b * 512 + rowStart + ldRow) * 768 + h * hd + kk;
        size_t boff = (size_t)(b * 512 + colStart + ldRow) * 768 + h * hd + kk;
        cp_async16(base + so0, Qh + aoff);
        cp_async16(base + so1, Qh + aoff + 8);
        cp_async16(base + 8192 + so0, Ql + aoff);
        cp_async16(base + 8192 + so1, Ql + aoff + 8);
        cp_async16(base + 16384 + so0, Kh + boff);
        cp_async16(base + 16384 + so1, Kh + boff + 8);
        cp_async16(base + 24576 + so0, Kl + boff);
        cp_async16(base + 24576 + so1, Kl + boff + 8);
    };

    const int rA = lane & 15, khA = lane >> 4;
    const int rB = lane & 7, khB = (lane >> 3) & 1;

    loadTile(0, 0);
    cp_commit();
    for (int kt = 0; kt < NIT; kt++) {
        if (kt + 1 < NIT) {
            loadTile((kt + 1) & 1, (kt + 1) * 32);
            cp_commit();
            cp_wait<1>();
        } else {
            cp_wait<0>();
        }
        __syncthreads();
        uint32_t tb = sb + (kt & 1) * 32768;
        HMMA_COMPUTE(tb)
        __syncthreads();
    }

    float* C = Sc + (size_t)z * 262144;
    const int g = lane >> 2, q4 = lane & 3;
    #pragma unroll
    for (int nf = 0; nf < 4; nf++) {
        int c = colStart + wn + 8 * nf + 2 * q4;
        #pragma unroll
        for (int mf = 0; mf < 4; mf++) {
            int r0 = rowStart + wm + 16 * mf + g;
            *(float2*)(C + (size_t)r0 * 512 + c) =
                make_float2(8.f * acc[mf][nf][0], 8.f * acc[mf][nf][1]);
            *(float2*)(C + (size_t)(r0 + 8) * 512 + c) =
                make_float2(8.f * acc[mf][nf][2], 8.f * acc[mf][nf][3]);
        }
    }
}

// ======================= attention PV GEMM: Out = P @ V (split output) =======================
__global__ void __launch_bounds__(256, 1) hmma_pv_kernel(
    const bf16* __restrict__ Ph, const bf16* __restrict__ Pl,
    const bf16* __restrict__ Vth, const bf16* __restrict__ Vtl,
    bf16* __restrict__ Oh, bf16* __restrict__ Ol, int H, int hd)
{
    extern __shared__ char smem[];
    uint32_t sb = smem_u32(smem);
    const int tid = threadIdx.x;
    const int z = blockIdx.z, b = z / H, h = z - b * H;
    const int rowStart = blockIdx.y * 128, colStart = blockIdx.x * 128;
    const int warp = tid >> 5, lane = tid & 31;
    const int wm = (warp & 1) * 64, wn = (warp >> 1) * 32;
    const int ldRow = tid >> 1;
    const int ldC0 = (tid & 1) * 2;
    const uint32_t so0 = swz(ldRow, ldC0);
    const uint32_t so1 = swz(ldRow, ldC0 + 1);

    float acc[4][4][4];
    #pragma unroll
    for (int i = 0; i < 4; i++)
        #pragma unroll
        for (int j = 0; j < 4; j++)
            #pragma unroll
            for (int c = 0; c < 4; c++) acc[i][j][c] = 0.f;

    const int NIT = 16;  // K = 512

    auto loadTile = [&](int buf, int k0) {
        uint32_t base = sb + buf * 32768;
        int kk = k0 + ldC0 * 8;
        size_t aoff = (size_t)z * 262144 + (size_t)(rowStart + ldRow) * 512 + kk;
        size_t boff = (size_t)(b * 768 + h * hd + colStart + ldRow) * 512 + kk;
        cp_async16(base + so0, Ph + aoff);
        cp_async16(base + so1, Ph + aoff + 8);
        cp_async16(base + 8192 + so0, Pl + aoff);
        cp_async16(base + 8192 + so1, Pl + aoff + 8);
        cp_async16(base + 16384 + so0, Vth + boff);
        cp_async16(base + 16384 + so1, Vth + boff + 8);
        cp_async16(base + 24576 + so0, Vtl + boff);
        cp_async16(base + 24576 + so1, Vtl + boff + 8);
    };

    const int rA = lane & 15, khA = lane >> 4;
    const int rB = lane & 7, khB = (lane >> 3) & 1;

    loadTile(0, 0);
    cp_commit();
    for (int kt = 0; kt < NIT; kt++) {
        if (kt + 1 < NIT) {
            loadTile((kt + 1) & 1, (kt + 1) * 32);
            cp_commit();
            cp_wait<1>();
        } else {
            cp_wait<0>();
        }
        __syncthreads();
        uint32_t tb = sb + (kt & 1) * 32768;
        HMMA_COMPUTE(tb)
        __syncthreads();
    }

    const int g = lane >> 2, q4 = lane & 3;
    #pragma unroll
    for (int nf = 0; nf < 4; nf++) {
        int cl = colStart + wn + 8 * nf + 2 * q4;
        if (cl < hd) {
            int c = h * hd + cl;
            #pragma unroll
            for (int mf = 0; mf < 4; mf++) {
                int r0 = b * 512 + rowStart + wm + 16 * mf + g;
                store_split2(Oh, Ol, (size_t)r0 * 768 + c, acc[mf][nf][0], acc[mf][nf][1]);
                store_split2(Oh, Ol, (size_t)(r0 + 8) * 768 + c, acc[mf][nf][2], acc[mf][nf][3]);
            }
        }
    }
}

// ======================= host =======================
extern "C" void kernel_launch(void* const* d_in, const int* in_sizes, int n_in,
                              void* d_out, int out_size)
{
    (void)n_in; (void)out_size;
    const float *text, *vtab, *atab;
    const float *aw[18];
    const float *fcw, *fcb, *f1w, *f1b, *f2w, *f2b, *catw, *catb;
    const int *vid, *aid;

    if (in_sizes[1] == MR) {
        text = (const float*)d_in[0];
        vid  = (const int*)d_in[1];
        aid  = (const int*)d_in[2];
        vtab = (const float*)d_in[3];
        atab = (const float*)d_in[4];
        for (int i = 0; i < 18; i++) aw[i] = (const float*)d_in[5 + i];
        fcw = (const float*)d_in[23]; fcb = (const float*)d_in[24];
        f1w = (const float*)d_in[25]; f1b = (const float*)d_in[26];
        f2w = (const float*)d_in[27]; f2b = (const float*)d_in[28];
        catw = (const float*)d_in[29]; catb = (const float*)d_in[30];
    } else {
        text = (const float*)d_in[0];
        vtab = (const float*)d_in[1];
        atab = (const float*)d_in[2];
        for (int i = 0; i < 18; i++) aw[i] = (const float*)d_in[3 + i];
        fcw = (const float*)d_in[21]; fcb = (const float*)d_in[22];
        f1w = (const float*)d_in[23]; f1b = (const float*)d_in[24];
        f2w = (const float*)d_in[25]; f2b = (const float*)d_in[26];
        catw = (const float*)d_in[27]; catb = (const float*)d_in[28];
        vid  = (const int*)d_in[29];
        aid  = (const int*)d_in[30];
    }

    cudaFuncSetAttribute(hmma_gemm_kernel<0,0>, cudaFuncAttributeMaxDynamicSharedMemorySize, HG_SMEM);
    cudaFuncSetAttribute(hmma_gemm_kernel<2,0>, cudaFuncAttributeMaxDynamicSharedMemorySize, HG_SMEM);
    cudaFuncSetAttribute(hmma_gemm_kernel<4,0>, cudaFuncAttributeMaxDynamicSharedMemorySize, HG_SMEM);
    cudaFuncSetAttribute(hmma_gemm_kernel<5,0>, cudaFuncAttributeMaxDynamicSharedMemorySize, HG_SMEM);
    cudaFuncSetAttribute(hmma_gemm_kernel<0,1>, cudaFuncAttributeMaxDynamicSharedMemorySize, HG_SMEM);
    cudaFuncSetAttribute(hmma_score_kernel, cudaFuncAttributeMaxDynamicSharedMemorySize, HG_SMEM);
    cudaFuncSetAttribute(hmma_pv_kernel, cudaFuncAttributeMaxDynamicSharedMemorySize, HG_SMEM);

    float *sc, *F1, *F2, *F3, *t1;
    bf16 *wth, *wtl, *cth, *ctl;
    bf16 *spt_h, *spt_l, *sev_h, *sev_l, *sea_h, *sea_l;
    bf16 *sq_h, *sq_l, *sk_h, *sk_l, *svt_h, *svt_l, *sp_h, *sp_l;
    bf16 *s1_h, *s1_l, *s2_h, *s2_l, *s3_h, *s3_l, *s4_h, *s4_l;
    bf16 *c1_h, *c1_l, *c2_h, *c2_l;
    cudaGetSymbolAddress((void**)&sc, g_sc);
    cudaGetSymbolAddress((void**)&F1, g_F1);
    cudaGetSymbolAddress((void**)&F2, g_F2);
    cudaGetSymbolAddress((void**)&F3, g_F3);
    cudaGetSymbolAddress((void**)&t1, g_t1);
    cudaGetSymbolAddress((void**)&wth, g_wth);
    cudaGetSymbolAddress((void**)&wtl, g_wtl);
    cudaGetSymbolAddress((void**)&cth, g_cth);
    cudaGetSymbolAddress((void**)&ctl, g_ctl);
    cudaGetSymbolAddress((void**)&spt_h, g_spt_h); cudaGetSymbolAddress((void**)&spt_l, g_spt_l);
    cudaGetSymbolAddress((void**)&sev_h, g_sev_h); cudaGetSymbolAddress((void**)&sev_l, g_sev_l);
    cudaGetSymbolAddress((void**)&sea_h, g_sea_h); cudaGetSymbolAddress((void**)&sea_l, g_sea_l);
    cudaGetSymbolAddress((void**)&sq_h, g_sq_h);   cudaGetSymbolAddress((void**)&sq_l, g_sq_l);
    cudaGetSymbolAddress((void**)&sk_h, g_sk_h);   cudaGetSymbolAddress((void**)&sk_l, g_sk_l);
    cudaGetSymbolAddress((void**)&svt_h, g_svt_h); cudaGetSymbolAddress((void**)&svt_l, g_svt_l);
    cudaGetSymbolAddress((void**)&sp_h, g_sp_h);   cudaGetSymbolAddress((void**)&sp_l, g_sp_l);
    cudaGetSymbolAddress((void**)&s1_h, g_s1_h);   cudaGetSymbolAddress((void**)&s1_l, g_s1_l);
    cudaGetSymbolAddress((void**)&s2_h, g_s2_h);   cudaGetSymbolAddress((void**)&s2_l, g_s2_l);
    cudaGetSymbolAddress((void**)&s3_h, g_s3_h);   cudaGetSymbolAddress((void**)&s3_l, g_s3_l);
    cudaGetSymbolAddress((void**)&s4_h, g_s4_h);   cudaGetSymbolAddress((void**)&s4_l, g_s4_l);
    cudaGetSymbolAddress((void**)&c1_h, g_c1_h);   cudaGetSymbolAddress((void**)&c1_l, g_c1_l);
    cudaGetSymbolAddress((void**)&c2_h, g_c2_h);   cudaGetSymbolAddress((void**)&c2_l, g_c2_l);

    const int EW = (NEL + 255) / 256;
    const int SW = (NEL / 2 + 255) / 256;
    const dim3 gHG(6, 128);

    // -------- weight prep --------
    const float* wsrc[12] = { aw[0], aw[2], aw[4], aw[6], aw[8], aw[10],
                              aw[12], aw[14], aw[16], fcw, f1w, f2w };
    for (int i = 0; i < 12; i++)
        wsplit_kernel<<<dim3(24, 24), 256>>>(wsrc[i], wth + (size_t)i * WSZ, wtl + (size_t)i * WSZ, 768);
    wsplit_kernel<<<dim3(48, 24), 256>>>(catw, cth, ctl, 1536);

    auto GEMM_F = [&](const bf16* Ah, const bf16* Al, int wi, const float* bi, float* Cc) {
        hmma_gemm_kernel<0,0><<<gHG, 256, HG_SMEM>>>(Ah, Al, nullptr, nullptr,
            wth + (size_t)wi * WSZ, wtl + (size_t)wi * WSZ, bi, Cc, nullptr, nullptr, 768);
    };
    auto GEMM_ROPE = [&](const bf16* Ah, const bf16* Al, int wi, const float* bi, bf16* oh, bf16* ol) {
        hmma_gemm_kernel<2,0><<<gHG, 256, HG_SMEM>>>(Ah, Al, nullptr, nullptr,
            wth + (size_t)wi * WSZ, wtl + (size_t)wi * WSZ, bi, nullptr, oh, ol, 768);
    };
    auto GEMM_VT = [&](const bf16* Ah, const bf16* Al, int wi, const float* bi) {
        hmma_gemm_kernel<4,0><<<gHG, 256, HG_SMEM>>>(Ah, Al, nullptr, nullptr,
            wth + (size_t)wi * WSZ, wtl + (size_t)wi * WSZ, bi, nullptr, svt_h, svt_l, 768);
    };
    auto GEMM_SILU = [&](const bf16* Ah, const bf16* Al, int wi, const float* bi, bf16* oh, bf16* ol) {
        hmma_gemm_kernel<5,0><<<gHG, 256, HG_SMEM>>>(Ah, Al, nullptr, nullptr,
            wth + (size_t)wi * WSZ, wtl + (size_t)wi * WSZ, bi, nullptr, oh, ol, 768);
    };
    auto CATGEMM = [&](const bf16* A1h, const bf16* A1l, const bf16* A2h, const bf16* A2l,
                       const float* bi, float* Cc) {
        hmma_gemm_kernel<0,1><<<gHG, 256, HG_SMEM>>>(A1h, A1l, A2h, A2l, cth, ctl, bi, Cc,
                                                     nullptr, nullptr, 1536);
    };
    auto ATT = [&](const bf16* qh_, const bf16* ql_, const bf16* kvh_, const bf16* kvl_,
                   int wbase, const float* bq, const float* bk, const float* bv,
                   bf16* outh, bf16* outl, int H, int hd) {
        GEMM_ROPE(qh_, ql_, wbase + 0, bq, sq_h, sq_l);
        GEMM_ROPE(kvh_, kvl_, wbase + 1, bk, sk_h, sk_l);
        GEMM_VT(kvh_, kvl_, wbase + 2, bv);
        hmma_score_kernel<<<dim3(4, 4, BB * H), 256, HG_SMEM>>>(sq_h, sq_l, sk_h, sk_l, sc, H, hd);
        softmax_split_kernel<<<BB * H * SS, 256>>>(sc, sp_h, sp_l);
        hmma_pv_kernel<<<dim3(hd == 768 ? 6 : 1, 4, BB * H), 256, HG_SMEM>>>(
            sp_h, sp_l, svt_h, svt_l, outh, outl, H, hd);
    };
    auto FFN = [&](float* x) {
        gate_split_kernel<<<MR, 256>>>(x, c1_h, c1_l);
        GEMM_SILU(c1_h, c1_l, 10, f1b, c2_h, c2_l);
        GEMM_F(c2_h, c2_l, 11, f2b, x);
    };

    // -------- forward --------
    asplit_kernel<<<SW, 256>>>(text, spt_h, spt_l);
    embed_split_kernel<<<EW, 256>>>(vtab, vid, sev_h, sev_l);
    embed_split_kernel<<<EW, 256>>>(atab, aid, sea_h, sea_l);

    // stage 1
    ATT(spt_h, spt_l, sev_h, sev_l, 0, aw[1], aw[3], aw[5], s1_h, s1_l, 1, 768);
    ATT(spt_h, spt_l, sea_h, sea_l, 3, aw[7], aw[9], aw[11], s2_h, s2_l, 1, 768);
    CATGEMM(s1_h, s1_l, s2_h, s2_l, catb, F1);
    FFN(F1);

    // stage 2
    ATT(s1_h, s1_l, s2_h, s2_l, 0, aw[1], aw[3], aw[5], s3_h, s3_l, 1, 768);
    ATT(s2_h, s2_l, s1_h, s1_l, 3, aw[7], aw[9], aw[11], s4_h, s4_l, 1, 768);
    CATGEMM(s3_h, s3_l, s4_h, s4_l, catb, F2);
    FFN(F2);

    // stage 3: F3 = mh8(F1, text) @ fcw + fcb, then FFN
    asplit_kernel<<<SW, 256>>>(F1, c1_h, c1_l);
    ATT(c1_h, c1_l, spt_h, spt_l, 6, aw[13], aw[15], aw[17], c2_h, c2_l, 8, 96);
    GEMM_F(c2_h, c2_l, 9, fcb, F3);
    FFN(F3);

    // es = text + F1 + F2 + F3; out = gate(es)
    add4_kernel<<<EW, 256>>>(text, F1, F2, F3, t1);
    gate_kernel<<<MR, 256>>>(t1, (float*)d_out);
}

// round 7
// speedup vs baseline: 3.5764x; 1.0339x over previous
#include <cuda_runtime.h>
#include <cuda_bf16.h>
#include <math.h>
#include <stdint.h>

#define DM 768
#define BB 32
#define SS 512
#define MR (BB*SS)          // 16384 rows
#define NEL (MR*DM)         // 12582912

typedef __nv_bfloat16 bf16;

// ======================= helpers =======================
__device__ __forceinline__ uint32_t smem_u32(const void* p) {
    uint32_t a;
    asm("{ .reg .u64 t; cvta.to.shared.u64 t, %1; cvt.u32.u64 %0, t; }" : "=r"(a) : "l"(p));
    return a;
}
__device__ __forceinline__ void cp_async16(uint32_t dst, const void* src) {
    asm volatile("cp.async.cg.shared.global [%0],[%1],16;" :: "r"(dst), "l"(src));
}
__device__ __forceinline__ void cp_commit() { asm volatile("cp.async.commit_group;"); }
template <int N>
__device__ __forceinline__ void cp_wait() { asm volatile("cp.async.wait_group %0;" :: "n"(N)); }
__device__ __forceinline__ void ldmx4(uint32_t& a0, uint32_t& a1, uint32_t& a2, uint32_t& a3, uint32_t addr) {
    asm volatile("ldmatrix.sync.aligned.m8n8.x4.shared.b16 {%0,%1,%2,%3},[%4];"
                 : "=r"(a0), "=r"(a1), "=r"(a2), "=r"(a3) : "r"(addr));
}
__device__ __forceinline__ void ldmx2(uint32_t& b0, uint32_t& b1, uint32_t addr) {
    asm volatile("ldmatrix.sync.aligned.m8n8.x2.shared.b16 {%0,%1},[%2];"
                 : "=r"(b0), "=r"(b1) : "r"(addr));
}
__device__ __forceinline__ void mma16816(float* c, uint32_t a0, uint32_t a1, uint32_t a2, uint32_t a3,
                                         uint32_t b0, uint32_t b1) {
    asm volatile("mma.sync.aligned.m16n8k16.row.col.f32.bf16.bf16.f32 "
                 "{%0,%1,%2,%3},{%4,%5,%6,%7},{%8,%9},{%0,%1,%2,%3};"
                 : "+f"(c[0]), "+f"(c[1]), "+f"(c[2]), "+f"(c[3])
                 : "r"(a0), "r"(a1), "r"(a2), "r"(a3), "r"(b0), "r"(b1));
}
__device__ __forceinline__ uint32_t swz(int row, int chunk) {
    return (uint32_t)(row * 64 + ((chunk ^ ((row >> 1) & 3)) << 4));
}
__device__ __forceinline__ void store_split2(bf16* Oh, bf16* Ol, size_t idx, float a, float b) {
    bf16 ha = __float2bfloat16(a);
    bf16 hb = __float2bfloat16(b);
    __nv_bfloat162 hh; hh.x = ha; hh.y = hb;
    __nv_bfloat162 ll;
    ll.x = __float2bfloat16(a - __bfloat162float(ha));
    ll.y = __float2bfloat16(b - __bfloat162float(hb));
    *(__nv_bfloat162*)(Oh + idx) = hh;
    *(__nv_bfloat162*)(Ol + idx) = ll;
}
__device__ __forceinline__ void split1(float x, bf16* h, bf16* l, size_t idx) {
    bf16 hh = __float2bfloat16(x);
    h[idx] = hh;
    l[idx] = __float2bfloat16(x - __bfloat162float(hh));
}

// ======================= scratch =======================
static __device__ float g_sc[67108864];
static __device__ float g_F1[NEL];
static __device__ float g_F2[NEL];
static __device__ float g_F3[NEL];
static __device__ float g_t1[NEL];

#define WSZ (768*768)
static __device__ bf16 g_wth[12 * WSZ];
static __device__ bf16 g_wtl[12 * WSZ];
static __device__ bf16 g_cth[768 * 1536];
static __device__ bf16 g_ctl[768 * 1536];

static __device__ bf16 g_spt_h[NEL], g_spt_l[NEL];
static __device__ bf16 g_sev_h[NEL], g_sev_l[NEL];
static __device__ bf16 g_sea_h[NEL], g_sea_l[NEL];
static __device__ bf16 g_sq_h[NEL],  g_sq_l[NEL];
static __device__ bf16 g_sk_h[NEL],  g_sk_l[NEL];
static __device__ bf16 g_svt_h[NEL + 65536], g_svt_l[NEL + 65536];
static __device__ bf16 g_sp_h[67108864], g_sp_l[67108864];
static __device__ bf16 g_s1_h[NEL], g_s1_l[NEL];
static __device__ bf16 g_s2_h[NEL], g_s2_l[NEL];
static __device__ bf16 g_s3_h[NEL], g_s3_l[NEL];
static __device__ bf16 g_s4_h[NEL], g_s4_l[NEL];
static __device__ bf16 g_c1_h[NEL], g_c1_l[NEL];
static __device__ bf16 g_c2_h[NEL], g_c2_l[NEL];

// ======================= elementwise =======================
__global__ void __launch_bounds__(256) embed_split_kernel(
    const float* __restrict__ tab, const int* __restrict__ ids,
    bf16* __restrict__ oh, bf16* __restrict__ ol)
{
    int i = blockIdx.x * 256 + threadIdx.x;
    if (i >= NEL) return;
    int row = i / DM;
    int d = i - row * DM;
    split1(tab[(size_t)ids[row] * DM + d], oh, ol, i);
}

__global__ void __launch_bounds__(256) asplit_kernel(
    const float* __restrict__ x, bf16* __restrict__ h, bf16* __restrict__ l)
{
    int i = blockIdx.x * 256 + threadIdx.x;
    if (i >= NEL / 2) return;
    float2 v = ((const float2*)x)[i];
    store_split2(h, l, (size_t)i * 2, v.x, v.y);
}

__global__ void __launch_bounds__(256) add4_kernel(
    const float* __restrict__ a, const float* __restrict__ b,
    const float* __restrict__ c, const float* __restrict__ d, float* __restrict__ o)
{
    int i = blockIdx.x * 256 + threadIdx.x;
    if (i < NEL) o[i] = a[i] + b[i] + c[i] + d[i];
}

__global__ void __launch_bounds__(256) wsplit_kernel(
    const float* __restrict__ W, bf16* __restrict__ Th, bf16* __restrict__ Tl, int K)
{
    __shared__ float t[32][33];
    int k0 = blockIdx.x * 32, n0 = blockIdx.y * 32;
    int tx = threadIdx.x & 31, ty = threadIdx.x >> 5;
    #pragma unroll
    for (int i = 0; i < 32; i += 8)
        t[ty + i][tx] = W[(size_t)(k0 + ty + i) * 768 + n0 + tx];
    __syncthreads();
    #pragma unroll
    for (int i = 0; i < 32; i += 8)
        split1(t[tx][ty + i], Th, Tl, (size_t)(n0 + ty + i) * K + k0 + tx);
}

__global__ void __launch_bounds__(256) softmax_split_kernel(
    const float* __restrict__ x, bf16* __restrict__ ph, bf16* __restrict__ pl)
{
    __shared__ float shm[8];
    __shared__ float shs[8];
    size_t row = blockIdx.x;
    const float* p = x + row * 512;
    int t = threadIdx.x;
    int lane = t & 31, wid = t >> 5;

    float a = p[t], b = p[t + 256];
    float m = fmaxf(a, b);
    #pragma unroll
    for (int o = 16; o; o >>= 1) m = fmaxf(m, __shfl_xor_sync(0xffffffffu, m, o));
    if (lane == 0) shm[wid] = m;
    __syncthreads();
    float m2 = shm[0];
    #pragma unroll
    for (int i = 1; i < 8; i++) m2 = fmaxf(m2, shm[i]);

    float e0 = __expf(a - m2), e1 = __expf(b - m2);
    float s = e0 + e1;
    #pragma unroll
    for (int o = 16; o; o >>= 1) s += __shfl_xor_sync(0xffffffffu, s, o);
    if (lane == 0) shs[wid] = s;
    __syncthreads();
    float s2 = 0.f;
    #pragma unroll
    for (int i = 0; i < 8; i++) s2 += shs[i];
    float inv = 1.f / s2;
    split1(e0 * inv, ph, pl, row * 512 + t);
    split1(e1 * inv, ph, pl, row * 512 + t + 256);
}

__global__ void __launch_bounds__(256) gate_kernel(
    const float* __restrict__ in, float* __restrict__ out)
{
    __shared__ float shm[8];
    __shared__ float shs[8];
    size_t row = blockIdx.x;
    const float* p = in + row * 768;
    float* q = out + row * 768;
    int t = threadIdx.x;
    int lane = t & 31, wid = t >> 5;

    float a = p[t], b = p[t + 256], c = p[t + 512];
    float m = fmaxf(fmaxf(a, b), c);
    #pragma unroll
    for (int o = 16; o; o >>= 1) m = fmaxf(m, __shfl_xor_sync(0xffffffffu, m, o));
    if (lane == 0) shm[wid] = m;
    __syncthreads();
    float m2 = shm[0];
    #pragma unroll
    for (int i = 1; i < 8; i++) m2 = fmaxf(m2, shm[i]);

    float e0 = __expf(a - m2), e1 = __expf(b - m2), e2 = __expf(c - m2);
    float s = e0 + e1 + e2;
    #pragma unroll
    for (int o = 16; o; o >>= 1) s += __shfl_xor_sync(0xffffffffu, s, o);
    if (lane == 0) shs[wid] = s;
    __syncthreads();
    float s2 = 0.f;
    #pragma unroll
    for (int i = 0; i < 8; i++) s2 += shs[i];
    float inv = 1.f / s2;
    q[t]       = a + a * e0 * inv;
    q[t + 256] = b + b * e1 * inv;
    q[t + 512] = c + c * e2 * inv;
}

__global__ void __launch_bounds__(256) gate_split_kernel(
    const float* __restrict__ in, bf16* __restrict__ oh, bf16* __restrict__ ol)
{
    __shared__ float shm[8];
    __shared__ float shs[8];
    size_t row = blockIdx.x;
    const float* p = in + row * 768;
    int t = threadIdx.x;
    int lane = t & 31, wid = t >> 5;

    float a = p[t], b = p[t + 256], c = p[t + 512];
    float m = fmaxf(fmaxf(a, b), c);
    #pragma unroll
    for (int o = 16; o; o >>= 1) m = fmaxf(m, __shfl_xor_sync(0xffffffffu, m, o));
    if (lane == 0) shm[wid] = m;
    __syncthreads();
    float m2 = shm[0];
    #pragma unroll
    for (int i = 1; i < 8; i++) m2 = fmaxf(m2, shm[i]);

    float e0 = __expf(a - m2), e1 = __expf(b - m2), e2 = __expf(c - m2);
    float s = e0 + e1 + e2;
    #pragma unroll
    for (int o = 16; o; o >>= 1) s += __shfl_xor_sync(0xffffffffu, s, o);
    if (lane == 0) shs[wid] = s;
    __syncthreads();
    float s2 = 0.f;
    #pragma unroll
    for (int i = 0; i < 8; i++) s2 += shs[i];
    float inv = 1.f / s2;
    split1(a + a * e0 * inv, oh, ol, row * 768 + t);
    split1(b + b * e1 * inv, oh, ol, row * 768 + t + 256);
    split1(c + c * e2 * inv, oh, ol, row * 768 + t + 512);
}

// ======================= HMMA core =======================
// 3-stage pipeline, 3x32KB buffers. Layout within buffer: Ah(8K) Al(8K) Bh(8K) Bl(8K).
#define HG_SMEM (3 * 32768)

// fragment-cached compute: per k-half load Bh+Bl frags once, stream A frags.
#define HMMA_COMPUTE(tb)                                                             \
    _Pragma("unroll")                                                                \
    for (int kc = 0; kc < 2; kc++) {                                                 \
        uint32_t bh0[4], bh1[4], bl0[4], bl1[4];                                     \
        _Pragma("unroll")                                                            \
        for (int nf = 0; nf < 4; nf++) {                                             \
            int r = wn + 8 * nf + rB;                                                \
            uint32_t co = (uint32_t)(r * 64 + (((kc * 2 + khB) ^ ((r >> 1) & 3)) << 4)); \
            ldmx2(bh0[nf], bh1[nf], (tb) + 16384 + co);                              \
            ldmx2(bl0[nf], bl1[nf], (tb) + 24576 + co);                              \
        }                                                                            \
        _Pragma("unroll")                                                            \
        for (int mf = 0; mf < 4; mf++) {                                             \
            int r = wm + 16 * mf + rA;                                               \
            uint32_t ao = (uint32_t)(r * 64 + (((kc * 2 + khA) ^ ((r >> 1) & 3)) << 4)); \
            uint32_t a0, a1, a2, a3;                                                 \
            ldmx4(a0, a1, a2, a3, (tb) + ao);                                        \
            _Pragma("unroll")                                                        \
            for (int nf = 0; nf < 4; nf++)                                           \
                mma16816(acc[mf][nf], a0, a1, a2, a3, bh0[nf], bh1[nf]);             \
            _Pragma("unroll")                                                        \
            for (int nf = 0; nf < 4; nf++)                                           \
                mma16816(acc[mf][nf], a0, a1, a2, a3, bl0[nf], bl1[nf]);             \
            ldmx4(a0, a1, a2, a3, (tb) + 8192 + ao);                                 \
            _Pragma("unroll")                                                        \
            for (int nf = 0; nf < 4; nf++)                                           \
                mma16816(acc[mf][nf], a0, a1, a2, a3, bh0[nf], bh1[nf]);             \
        }                                                                            \
    }

// 3-stage mainloop: one __syncthreads per iteration.
// iter kt: wait tile kt ready -> barrier -> issue load kt+2 (into buf (kt-1)%3,
// finished by all warps before this barrier) -> compute tile kt.
#define HMMA_MAINLOOP()                                                              \
    loadTile(0, 0); cp_commit();                                                     \
    loadTile(1, 32); cp_commit();                                                    \
    for (int kt = 0; kt < NIT; kt++) {                                               \
        if (kt == NIT - 1) cp_wait<0>(); else cp_wait<1>();                          \
        __syncthreads();                                                             \
        if (kt + 2 < NIT) { loadTile((kt + 2) % 3, (kt + 2) * 32); cp_commit(); }    \
        uint32_t tb = sb + (uint32_t)((kt % 3) * 32768);                             \
        HMMA_COMPUTE(tb)                                                             \
    }

// ======================= projection GEMM =======================
// EPI: 0 = fp32+bias ; 2 = rope+split ; 4 = V-transpose+split ; 5 = silu+split
template <int EPI, int CAT>
__global__ void __launch_bounds__(256, 1) hmma_gemm_kernel(
    const bf16* __restrict__ A1h, const bf16* __restrict__ A1l,
    const bf16* __restrict__ A2h, const bf16* __restrict__ A2l,
    const bf16* __restrict__ Wh, const bf16* __restrict__ Wl,
    const float* __restrict__ bias, float* __restrict__ C,
    bf16* __restrict__ Oh, bf16* __restrict__ Ol, int K)
{
    extern __shared__ char smem[];
    uint32_t sb = smem_u32(smem);
    const int tid = threadIdx.x;
    const int rowStart = blockIdx.y * 128, colStart = blockIdx.x * 128;
    const int warp = tid >> 5, lane = tid & 31;
    const int wm = (warp & 1) * 64, wn = (warp >> 1) * 32;
    const int ldRow = tid >> 1;
    const int ldC0 = (tid & 1) * 2;
    const uint32_t so0 = swz(ldRow, ldC0);
    const uint32_t so1 = swz(ldRow, ldC0 + 1);

    float acc[4][4][4];
    #pragma unroll
    for (int i = 0; i < 4; i++)
        #pragma unroll
        for (int j = 0; j < 4; j++)
            #pragma unroll
            for (int c = 0; c < 4; c++) acc[i][j][c] = 0.f;

    const int NIT = K / 32;

    auto loadTile = [&](int buf, int k0) {
        uint32_t base = sb + buf * 32768;
        int kk = k0 + ldC0 * 8;
        const bf16 *ph, *pl; size_t aoff;
        if (!CAT) {
            ph = A1h; pl = A1l; aoff = (size_t)(rowStart + ldRow) * K + kk;
        } else if (k0 < 768) {
            ph = A1h; pl = A1l; aoff = (size_t)(rowStart + ldRow) * 768 + kk;
        } else {
            ph = A2h; pl = A2l; aoff = (size_t)(rowStart + ldRow) * 768 + (kk - 768);
        }
        cp_async16(base + so0, ph + aoff);
        cp_async16(base + so1, ph + aoff + 8);
        cp_async16(base + 8192 + so0, pl + aoff);
        cp_async16(base + 8192 + so1, pl + aoff + 8);
        size_t boff = (size_t)(colStart + ldRow) * K + kk;
        cp_async16(base + 16384 + so0, Wh + boff);
        cp_async16(base + 16384 + so1, Wh + boff + 8);
        cp_async16(base + 24576 + so0, Wl + boff);
        cp_async16(base + 24576 + so1, Wl + boff + 8);
    };

    const int rA = lane & 15, khA = lane >> 4;
    const int rB = lane & 7, khB = (lane >> 3) & 1;

    HMMA_MAINLOOP()

    const int g = lane >> 2, q4 = lane & 3;
    const float coef = -0.034603417655075f; // -2*log2(10000)/768
    #pragma unroll
    for (int nf = 0; nf < 4; nf++) {
        int c = colStart + wn + 8 * nf + 2 * q4;
        float bx = bias[c], by = bias[c + 1];
        #pragma unroll
        for (int mf = 0; mf < 4; mf++) {
            int r0 = rowStart + wm + 16 * mf + g;
            float v0 = acc[mf][nf][0] + bx;
            float v1 = acc[mf][nf][1] + by;
            float v2 = acc[mf][nf][2] + bx;
            float v3 = acc[mf][nf][3] + by;
            if (EPI == 0) {
                *(float2*)(C + (size_t)r0 * 768 + c) = make_float2(v0, v1);
                *(float2*)(C + (size_t)(r0 + 8) * 768 + c) = make_float2(v2, v3);
            } else if (EPI == 2) {
                float theta = exp2f(coef * (float)(c >> 1));
                int s0 = r0 & (SS - 1);
                float sn, cs;
                sincosf((float)s0 * theta, &sn, &cs);
                float x0 = v0 * cs - v1 * sn, x1 = v1 * cs + v0 * sn;
                sincosf((float)(s0 + 8) * theta, &sn, &cs);
                float x2 = v2 * cs - v3 * sn, x3 = v3 * cs + v2 * sn;
                store_split2(Oh, Ol, (size_t)r0 * 768 + c, x0, x1);
                store_split2(Oh, Ol, (size_t)(r0 + 8) * 768 + c, x2, x3);
            } else if (EPI == 4) {
                int b = r0 >> 9, s0 = r0 & (SS - 1);
                split1(v0, Oh, Ol, ((size_t)(b * 768 + c)) * 512 + s0);
                split1(v1, Oh, Ol, ((size_t)(b * 768 + c + 1)) * 512 + s0);
                split1(v2, Oh, Ol, ((size_t)(b * 768 + c)) * 512 + s0 + 8);
                split1(v3, Oh, Ol, ((size_t)(b * 768 + c + 1)) * 512 + s0 + 8);
            } else { // EPI 5: silu + split
                v0 *= 1.f / (1.f + __expf(-v0));
                v1 *= 1.f / (1.f + __expf(-v1));
                v2 *= 1.f / (1.f + __expf(-v2));
                v3 *= 1.f / (1.f + __expf(-v3));
                store_split2(Oh, Ol, (size_t)r0 * 768 + c, v0, v1);
                store_split2(Oh, Ol, (size_t)(r0 + 8) * 768 + c, v2, v3);
            }
        }
    }
}

// ======================= score GEMM: Sc = 8 * Q @ K^T =======================
__global__ void __launch_bounds__(256, 1) hmma_score_kernel(
    const bf16* __restrict__ Qh, const bf16* __restrict__ Ql,
    const bf16* __restrict__ Kh, const bf16* __restrict__ Kl,
    float* __restrict__ Sc, int H, int hd)
{
    extern __shared__ char smem[];
    uint32_t sb = smem_u32(smem);
    const int tid = threadIdx.x;
    const int z = blockIdx.z, b = z / H, h = z - b * H;
    const int rowStart = blockIdx.y * 128, colStart = blockIdx.x * 128;
    const int warp = tid >> 5, lane = tid & 31;
    const int wm = (warp & 1) * 64, wn = (warp >> 1) * 32;
    const int ldRow = tid >> 1;
    const int ldC0 = (tid & 1) * 2;
    const uint32_t so0 = swz(ldRow, ldC0);
    const uint32_t so1 = swz(ldRow, ldC0 + 1);

    float acc[4][4][4];
    #pragma unroll
    for (int i = 0; i < 4; i++)
        #pragma unroll
        for (int j = 0; j < 4; j++)
            #pragma unroll
            for (int c = 0; c < 4; c++) acc[i][j][c] = 0.f;

    const int NIT = hd / 32;

    auto loadTile = [&](int buf, int k0) {
        uint32_t base = sb + buf * 32768;
        int kk = k0 + ldC0 * 8;
        size_t aoff = (size_t)(b * 512 + rowStart + ldRow) * 768 + h * hd + kk;
        size_t boff = (size_t)(b * 512 + colStart + ldRow) * 768 + h * hd + kk;
        cp_async16(base + so0, Qh + aoff);
        cp_async16(base + so1, Qh + aoff + 8);
        cp_async16(base + 8192 + so0, Ql + aoff);
        cp_async16(base + 8192 + so1, Ql + aoff + 8);
        cp_async16(base + 16384 + so0, Kh + boff);
        cp_async16(base + 16384 + so1, Kh + boff + 8);
        cp_async16(base + 24576 + so0, Kl + boff);
        cp_async16(base + 24576 + so1, Kl + boff + 8);
    };

    const int rA = lane & 15, khA = lane >> 4;
    const int rB = lane & 7, khB = (lane >> 3) & 1;

    HMMA_MAINLOOP()

    float* C = Sc + (size_t)z * 262144;
    const int g = lane >> 2, q4 = lane & 3;
    #pragma unroll
    for (int nf = 0; nf < 4; nf++) {
        int c = colStart + wn + 8 * nf + 2 * q4;
        #pragma unroll
        for (int mf = 0; mf < 4; mf++) {
            int r0 = rowStart + wm + 16 * mf + g;
            *(float2*)(C + (size_t)r0 * 512 + c) =
                make_float2(8.f * acc[mf][nf][0], 8.f * acc[mf][nf][1]);
            *(float2*)(C + (size_t)(r0 + 8) * 512 + c) =
                make_float2(8.f * acc[mf][nf][2], 8.f * acc[mf][nf][3]);
        }
    }
}

// ======================= PV GEMM: Out = P @ V (split output) =======================
__global__ void __launch_bounds__(256, 1) hmma_pv_kernel(
    const bf16* __restrict__ Ph, const bf16* __restrict__ Pl,
    const bf16* __restrict__ Vth, const bf16* __restrict__ Vtl,
    bf16* __restrict__ Oh, bf16* __restrict__ Ol, int H, int hd)
{
    extern __shared__ char smem[];
    uint32_t sb = smem_u32(smem);
    const int tid = threadIdx.x;
    const int z = blockIdx.z, b = z / H, h = z - b * H;
    const int rowStart = blockIdx.y * 128, colStart = blockIdx.x * 128;
    const int warp = tid >> 5, lane = tid & 31;
    const int wm = (warp & 1) * 64, wn = (warp >> 1) * 32;
    const int ldRow = tid >> 1;
    const int ldC0 = (tid & 1) * 2;
    const uint32_t so0 = swz(ldRow, ldC0);
    const uint32_t so1 = swz(ldRow, ldC0 + 1);

    float acc[4][4][4];
    #pragma unroll
    for (int i = 0; i < 4; i++)
        #pragma unroll
        for (int j = 0; j < 4; j++)
            #pragma unroll
            for (int c = 0; c < 4; c++) acc[i][j][c] = 0.f;

    const int NIT = 16;  // K = 512

    auto loadTile = [&](int buf, int k0) {
        uint32_t base = sb + buf * 32768;
        int kk = k0 + ldC0 * 8;
        size_t aoff = (size_t)z * 262144 + (size_t)(rowStart + ldRow) * 512 + kk;
        size_t boff = (size_t)(b * 768 + h * hd + colStart + ldRow) * 512 + kk;
        cp_async16(base + so0, Ph + aoff);
        cp_async16(base + so1, Ph + aoff + 8);
        cp_async16(base + 8192 + so0, Pl + aoff);
        cp_async16(base + 8192 + so1, Pl + aoff + 8);
        cp_async16(base + 16384 + so0, Vth + boff);
        cp_async16(base + 16384 + so1, Vth + boff + 8);
        cp_async16(base + 24576 + so0, Vtl + boff);
        cp_async16(base + 24576 + so1, Vtl + boff + 8);
    };

    const int rA = lane & 15, khA = lane >> 4;
    const int rB = lane & 7, khB = (lane >> 3) & 1;

    HMMA_MAINLOOP()

    const int g = lane >> 2, q4 = lane & 3;
    #pragma unroll
    for (int nf = 0; nf < 4; nf++) {
        int cl = colStart + wn + 8 * nf + 2 * q4;
        if (cl < hd) {
            int c = h * hd + cl;
            #pragma unroll
            for (int mf = 0; mf < 4; mf++) {
                int r0 = b * 512 + rowStart + wm + 16 * mf + g;
                store_split2(Oh, Ol, (size_t)r0 * 768 + c, acc[mf][nf][0], acc[mf][nf][1]);
                store_split2(Oh, Ol, (size_t)(r0 + 8) * 768 + c, acc[mf][nf][2], acc[mf][nf][3]);
            }
        }
    }
}

// ======================= host =======================
extern "C" void kernel_launch(void* const* d_in, const int* in_sizes, int n_in,
                              void* d_out, int out_size)
{
    (void)n_in; (void)out_size;
    const float *text, *vtab, *atab;
    const float *aw[18];
    const float *fcw, *fcb, *f1w, *f1b, *f2w, *f2b, *catw, *catb;
    const int *vid, *aid;

    if (in_sizes[1] == MR) {
        text = (const float*)d_in[0];
        vid  = (const int*)d_in[1];
        aid  = (const int*)d_in[2];
        vtab = (const float*)d_in[3];
        atab = (const float*)d_in[4];
        for (int i = 0; i < 18; i++) aw[i] = (const float*)d_in[5 + i];
        fcw = (const float*)d_in[23]; fcb = (const float*)d_in[24];
        f1w = (const float*)d_in[25]; f1b = (const float*)d_in[26];
        f2w = (const float*)d_in[27]; f2b = (const float*)d_in[28];
        catw = (const float*)d_in[29]; catb = (const float*)d_in[30];
    } else {
        text = (const float*)d_in[0];
        vtab = (const float*)d_in[1];
        atab = (const float*)d_in[2];
        for (int i = 0; i < 18; i++) aw[i] = (const float*)d_in[3 + i];
        fcw = (const float*)d_in[21]; fcb = (const float*)d_in[22];
        f1w = (const float*)d_in[23]; f1b = (const float*)d_in[24];
        f2w = (const float*)d_in[25]; f2b = (const float*)d_in[26];
        catw = (const float*)d_in[27]; catb = (const float*)d_in[28];
        vid  = (const int*)d_in[29];
        aid  = (const int*)d_in[30];
    }

    cudaFuncSetAttribute(hmma_gemm_kernel<0,0>, cudaFuncAttributeMaxDynamicSharedMemorySize, HG_SMEM);
    cudaFuncSetAttribute(hmma_gemm_kernel<2,0>, cudaFuncAttributeMaxDynamicSharedMemorySize, HG_SMEM);
    cudaFuncSetAttribute(hmma_gemm_kernel<4,0>, cudaFuncAttributeMaxDynamicSharedMemorySize, HG_SMEM);
    cudaFuncSetAttribute(hmma_gemm_kernel<5,0>, cudaFuncAttributeMaxDynamicSharedMemorySize, HG_SMEM);
    cudaFuncSetAttribute(hmma_gemm_kernel<0,1>, cudaFuncAttributeMaxDynamicSharedMemorySize, HG_SMEM);
    cudaFuncSetAttribute(hmma_score_kernel, cudaFuncAttributeMaxDynamicSharedMemorySize, HG_SMEM);
    cudaFuncSetAttribute(hmma_pv_kernel, cudaFuncAttributeMaxDynamicSharedMemorySize, HG_SMEM);

    float *sc, *F1, *F2, *F3, *t1;
    bf16 *wth, *wtl, *cth, *ctl;
    bf16 *spt_h, *spt_l, *sev_h, *sev_l, *sea_h, *sea_l;
    bf16 *sq_h, *sq_l, *sk_h, *sk_l, *svt_h, *svt_l, *sp_h, *sp_l;
    bf16 *s1_h, *s1_l, *s2_h, *s2_l, *s3_h, *s3_l, *s4_h, *s4_l;
    bf16 *c1_h, *c1_l, *c2_h, *c2_l;
    cudaGetSymbolAddress((void**)&sc, g_sc);
    cudaGetSymbolAddress((void**)&F1, g_F1);
    cudaGetSymbolAddress((void**)&F2, g_F2);
    cudaGetSymbolAddress((void**)&F3, g_F3);
    cudaGetSymbolAddress((void**)&t1, g_t1);
    cudaGetSymbolAddress((void**)&wth, g_wth);
    cudaGetSymbolAddress((void**)&wtl, g_wtl);
    cudaGetSymbolAddress((void**)&cth, g_cth);
    cudaGetSymbolAddress((void**)&ctl, g_ctl);
    cudaGetSymbolAddress((void**)&spt_h, g_spt_h); cudaGetSymbolAddress((void**)&spt_l, g_spt_l);
    cudaGetSymbolAddress((void**)&sev_h, g_sev_h); cudaGetSymbolAddress((void**)&sev_l, g_sev_l);
    cudaGetSymbolAddress((void**)&sea_h, g_sea_h); cudaGetSymbolAddress((void**)&sea_l, g_sea_l);
    cudaGetSymbolAddress((void**)&sq_h, g_sq_h);   cudaGetSymbolAddress((void**)&sq_l, g_sq_l);
    cudaGetSymbolAddress((void**)&sk_h, g_sk_h);   cudaGetSymbolAddress((void**)&sk_l, g_sk_l);
    cudaGetSymbolAddress((void**)&svt_h, g_svt_h); cudaGetSymbolAddress((void**)&svt_l, g_svt_l);
    cudaGetSymbolAddress((void**)&sp_h, g_sp_h);   cudaGetSymbolAddress((void**)&sp_l, g_sp_l);
    cudaGetSymbolAddress((void**)&s1_h, g_s1_h);   cudaGetSymbolAddress((void**)&s1_l, g_s1_l);
    cudaGetSymbolAddress((void**)&s2_h, g_s2_h);   cudaGetSymbolAddress((void**)&s2_l, g_s2_l);
    cudaGetSymbolAddress((void**)&s3_h, g_s3_h);   cudaGetSymbolAddress((void**)&s3_l, g_s3_l);
    cudaGetSymbolAddress((void**)&s4_h, g_s4_h);   cudaGetSymbolAddress((void**)&s4_l, g_s4_l);
    cudaGetSymbolAddress((void**)&c1_h, g_c1_h);   cudaGetSymbolAddress((void**)&c1_l, g_c1_l);
    cudaGetSymbolAddress((void**)&c2_h, g_c2_h);   cudaGetSymbolAddress((void**)&c2_l, g_c2_l);

    const int EW = (NEL + 255) / 256;
    const int SW = (NEL / 2 + 255) / 256;
    const dim3 gHG(6, 128);

    // -------- weight prep --------
    const float* wsrc[12] = { aw[0], aw[2], aw[4], aw[6], aw[8], aw[10],
                              aw[12], aw[14], aw[16], fcw, f1w, f2w };
    for (int i = 0; i < 12; i++)
        wsplit_kernel<<<dim3(24, 24), 256>>>(wsrc[i], wth + (size_t)i * WSZ, wtl + (size_t)i * WSZ, 768);
    wsplit_kernel<<<dim3(48, 24), 256>>>(catw, cth, ctl, 1536);

    auto GEMM_F = [&](const bf16* Ah, const bf16* Al, int wi, const float* bi, float* Cc) {
        hmma_gemm_kernel<0,0><<<gHG, 256, HG_SMEM>>>(Ah, Al, nullptr, nullptr,
            wth + (size_t)wi * WSZ, wtl + (size_t)wi * WSZ, bi, Cc, nullptr, nullptr, 768);
    };
    auto GEMM_ROPE = [&](const bf16* Ah, const bf16* Al, int wi, const float* bi, bf16* oh, bf16* ol) {
        hmma_gemm_kernel<2,0><<<gHG, 256, HG_SMEM>>>(Ah, Al, nullptr, nullptr,
            wth + (size_t)wi * WSZ, wtl + (size_t)wi * WSZ, bi, nullptr, oh, ol, 768);
    };
    auto GEMM_VT = [&](const bf16* Ah, const bf16* Al, int wi, const float* bi) {
        hmma_gemm_kernel<4,0><<<gHG, 256, HG_SMEM>>>(Ah, Al, nullptr, nullptr,
            wth + (size_t)wi * WSZ, wtl + (size_t)wi * WSZ, bi, nullptr, svt_h, svt_l, 768);
    };
    auto GEMM_SILU = [&](const bf16* Ah, const bf16* Al, int wi, const float* bi, bf16* oh, bf16* ol) {
        hmma_gemm_kernel<5,0><<<gHG, 256, HG_SMEM>>>(Ah, Al, nullptr, nullptr,
            wth + (size_t)wi * WSZ, wtl + (size_t)wi * WSZ, bi, nullptr, oh, ol, 768);
    };
    auto CATGEMM = [&](const bf16* A1h, const bf16* A1l, const bf16* A2h, const bf16* A2l,
                       const float* bi, float* Cc) {
        hmma_gemm_kernel<0,1><<<gHG, 256, HG_SMEM>>>(A1h, A1l, A2h, A2l, cth, ctl, bi, Cc,
                                                     nullptr, nullptr, 1536);
    };
    auto ATT = [&](const bf16* qh_, const bf16* ql_, const bf16* kvh_, const bf16* kvl_,
                   int wbase, const float* bq, const float* bk, const float* bv,
                   bf16* outh, bf16* outl, int H, int hd) {
        GEMM_ROPE(qh_, ql_, wbase + 0, bq, sq_h, sq_l);
        GEMM_ROPE(kvh_, kvl_, wbase + 1, bk, sk_h, sk_l);
        GEMM_VT(kvh_, kvl_, wbase + 2, bv);
        hmma_score_kernel<<<dim3(4, 4, BB * H), 256, HG_SMEM>>>(sq_h, sq_l, sk_h, sk_l, sc, H, hd);
        softmax_split_kernel<<<BB * H * SS, 256>>>(sc, sp_h, sp_l);
        hmma_pv_kernel<<<dim3(hd == 768 ? 6 : 1, 4, BB * H), 256, HG_SMEM>>>(
            sp_h, sp_l, svt_h, svt_l, outh, outl, H, hd);
    };
    auto FFN = [&](float* x) {
        gate_split_kernel<<<MR, 256>>>(x, c1_h, c1_l);
        GEMM_SILU(c1_h, c1_l, 10, f1b, c2_h, c2_l);
        GEMM_F(c2_h, c2_l, 11, f2b, x);
    };

    // -------- forward --------
    asplit_kernel<<<SW, 256>>>(text, spt_h, spt_l);
    embed_split_kernel<<<EW, 256>>>(vtab, vid, sev_h, sev_l);
    embed_split_kernel<<<EW, 256>>>(atab, aid, sea_h, sea_l);

    // stage 1
    ATT(spt_h, spt_l, sev_h, sev_l, 0, aw[1], aw[3], aw[5], s1_h, s1_l, 1, 768);
    ATT(spt_h, spt_l, sea_h, sea_l, 3, aw[7], aw[9], aw[11], s2_h, s2_l, 1, 768);
    CATGEMM(s1_h, s1_l, s2_h, s2_l, catb, F1);
    FFN(F1);

    // stage 2
    ATT(s1_h, s1_l, s2_h, s2_l, 0, aw[1], aw[3], aw[5], s3_h, s3_l, 1, 768);
    ATT(s2_h, s2_l, s1_h, s1_l, 3, aw[7], aw[9], aw[11], s4_h, s4_l, 1, 768);
    CATGEMM(s3_h, s3_l, s4_h, s4_l, catb, F2);
    FFN(F2);

    // stage 3: F3 = mh8(F1, text) @ fcw + fcb, then FFN
    asplit_kernel<<<SW, 256>>>(F1, c1_h, c1_l);
    ATT(c1_h, c1_l, spt_h, spt_l, 6, aw[13], aw[15], aw[17], c2_h, c2_l, 8, 96);
    GEMM_F(c2_h, c2_l, 9, fcb, F3);
    FFN(F3);

    // es = text + F1 + F2 + F3; out = gate(es)
    add4_kernel<<<EW, 256>>>(text, F1, F2, F3, t1);
    gate_kernel<<<MR, 256>>>(t1, (float*)d_out);
}